// round 2
// baseline (speedup 1.0000x reference)
#include <cuda_runtime.h>
#include <cuda_bf16.h>

// Problem constants (fixed shapes per reference)
constexpr int N_NODES = 50000;
constexpr int N_EDGES = 1600000;
constexpr int IN_DIM  = 256;
constexpr int HD      = 128;   // HEADS * OUT_DIM

// ---------------- scratch (static device globals; no runtime alloc) ----------
__device__ float4 g_h[N_NODES * (HD / 4)];      // h[n, :] as 32 float4 per node (25.6 MB)
__device__ float4 g_ssrc[N_NODES];              // per-node src scores, 4 heads
__device__ float4 g_sdst[N_NODES];              // per-node dst scores, 4 heads
__device__ float4 g_ex[N_EDGES];                // exp(e) per edge, 4 heads (25.6 MB)
__device__ float4 g_denom[N_NODES];             // softmax denominators, 4 heads

// ---------------- helpers ----------------------------------------------------
__device__ __forceinline__ void red_add_v4(float* addr, float4 v) {
#if __CUDA_ARCH__ >= 900
    asm volatile("red.global.add.v4.f32 [%0], {%1,%2,%3,%4};"
                 :: "l"(addr), "f"(v.x), "f"(v.y), "f"(v.z), "f"(v.w) : "memory");
#else
    atomicAdd(addr + 0, v.x); atomicAdd(addr + 1, v.y);
    atomicAdd(addr + 2, v.z); atomicAdd(addr + 3, v.w);
#endif
}

// ---------------- 1. GEMM: h = x @ W^T  (NT gemm, both K-major) --------------
// BM=64, BN=128(full), BK=32, 256 threads, 8x4 micro-tile per thread.
__global__ __launch_bounds__(256) void gemm_kernel(const float* __restrict__ x,
                                                   const float* __restrict__ W) {
    __shared__ float As[32][64 + 4];    // [k][n], padded
    __shared__ float Bs[32][128 + 4];   // [k][m], padded

    const int tid = threadIdx.x;
    const int tx = tid & 31;        // output col group (x4)
    const int ty = tid >> 5;        // output row group (x8)
    const int nBase = blockIdx.x * 64;

    const int lr = tid >> 3;        // 0..31 (row within load tile)
    const int lk = (tid & 7) << 2;  // 0,4,...,28 (k offset)

    float acc[8][4];
#pragma unroll
    for (int i = 0; i < 8; i++)
#pragma unroll
        for (int j = 0; j < 4; j++) acc[i][j] = 0.f;

    for (int k0 = 0; k0 < IN_DIM; k0 += 32) {
        // load x tile (64 rows)
#pragma unroll
        for (int it = 0; it < 2; it++) {
            int r = lr + it * 32;
            int row = nBase + r;
            float4 v = make_float4(0.f, 0.f, 0.f, 0.f);
            if (row < N_NODES)
                v = *reinterpret_cast<const float4*>(&x[(long)row * IN_DIM + k0 + lk]);
            As[lk + 0][r] = v.x; As[lk + 1][r] = v.y;
            As[lk + 2][r] = v.z; As[lk + 3][r] = v.w;
        }
        // load W tile (128 rows, always in bounds)
#pragma unroll
        for (int it = 0; it < 4; it++) {
            int r = lr + it * 32;
            float4 v = *reinterpret_cast<const float4*>(&W[(long)r * IN_DIM + k0 + lk]);
            Bs[lk + 0][r] = v.x; Bs[lk + 1][r] = v.y;
            Bs[lk + 2][r] = v.z; Bs[lk + 3][r] = v.w;
        }
        __syncthreads();

#pragma unroll
        for (int k = 0; k < 32; k++) {
            float4 b  = *reinterpret_cast<const float4*>(&Bs[k][tx * 4]);
            float4 a0 = *reinterpret_cast<const float4*>(&As[k][ty * 8]);
            float4 a1 = *reinterpret_cast<const float4*>(&As[k][ty * 8 + 4]);
            float av[8] = {a0.x, a0.y, a0.z, a0.w, a1.x, a1.y, a1.z, a1.w};
            float bv[4] = {b.x, b.y, b.z, b.w};
#pragma unroll
            for (int i = 0; i < 8; i++)
#pragma unroll
                for (int j = 0; j < 4; j++) acc[i][j] += av[i] * bv[j];
        }
        __syncthreads();
    }

#pragma unroll
    for (int i = 0; i < 8; i++) {
        int row = nBase + ty * 8 + i;
        if (row < N_NODES)
            g_h[row * 32 + tx] = make_float4(acc[i][0], acc[i][1], acc[i][2], acc[i][3]);
    }
}

// ---------------- 2. per-node attention scores (warp per node) ---------------
// Also zeroes g_denom (runs before edge pass 1 on the same stream).
__global__ __launch_bounds__(256) void scores_kernel(const float* __restrict__ a_src,
                                                     const float* __restrict__ a_dst) {
    int warp = (blockIdx.x * blockDim.x + threadIdx.x) >> 5;
    if (warp >= N_NODES) return;
    int lane = threadIdx.x & 31;
    int head = lane >> 3;
    int sub  = lane & 7;

    float4 hv = g_h[warp * 32 + lane];
    const float4* as4 = reinterpret_cast<const float4*>(a_src);
    const float4* ad4 = reinterpret_cast<const float4*>(a_dst);
    float4 av = as4[head * 8 + sub];
    float4 dv = ad4[head * 8 + sub];

    float ps = hv.x * av.x + hv.y * av.y + hv.z * av.z + hv.w * av.w;
    float pd = hv.x * dv.x + hv.y * dv.y + hv.z * dv.z + hv.w * dv.w;
#pragma unroll
    for (int o = 4; o >= 1; o >>= 1) {
        ps += __shfl_xor_sync(0xffffffffu, ps, o);
        pd += __shfl_xor_sync(0xffffffffu, pd, o);
    }
    if (sub == 0) {
        reinterpret_cast<float*>(&g_ssrc[warp])[head] = ps;
        reinterpret_cast<float*>(&g_sdst[warp])[head] = pd;
    }
    if (lane == 0) g_denom[warp] = make_float4(0.f, 0.f, 0.f, 0.f);
}

// ---------------- 3. zero the output accumulator -----------------------------
__global__ void zero_out_kernel(float4* out) {
    int i = blockIdx.x * blockDim.x + threadIdx.x;
    if (i < N_NODES * (HD / 4)) out[i] = make_float4(0.f, 0.f, 0.f, 0.f);
}

// ---------------- 4. edge pass 1: exp(e), denom accumulation -----------------
// Softmax is shift-invariant; e = tanh(.)*w in (-1,1) so exp(e) never
// overflows -> the reference's segment_max is mathematically unnecessary.
__global__ __launch_bounds__(256) void edge_score_kernel(const int* __restrict__ idx,
                                                         const float* __restrict__ wts) {
    int e = blockIdx.x * blockDim.x + threadIdx.x;
    if (e >= N_EDGES) return;
    int2 p = reinterpret_cast<const int2*>(idx)[e];   // adj_indices as int32 pairs
    int s = p.x, d = p.y;
    float w = wts[e];
    float4 a = g_ssrc[s];
    float4 b = g_sdst[d];
    float4 ex;
    ex.x = expf(tanhf(a.x + b.x) * w);
    ex.y = expf(tanhf(a.y + b.y) * w);
    ex.z = expf(tanhf(a.z + b.z) * w);
    ex.w = expf(tanhf(a.w + b.w) * w);
    g_ex[e] = ex;
    red_add_v4(reinterpret_cast<float*>(&g_denom[d]), ex);
}

// ---------------- 5. edge pass 2: weighted scatter-add (warp per edge) -------
__global__ __launch_bounds__(256) void aggregate_kernel(const int* __restrict__ idx,
                                                        float* __restrict__ out) {
    int warp = (blockIdx.x * blockDim.x + threadIdx.x) >> 5;
    if (warp >= N_EDGES) return;
    int lane = threadIdx.x & 31;
    int head = lane >> 3;

    int2 p = reinterpret_cast<const int2*>(idx)[warp];  // uniform in warp
    int s = p.x, d = p.y;

    float ex  = reinterpret_cast<const float*>(&g_ex[warp])[head];
    float den = reinterpret_cast<const float*>(&g_denom[d])[head];
    float alpha = ex / den;

    float4 hv = g_h[s * 32 + lane];
    float4 m  = make_float4(alpha * hv.x, alpha * hv.y, alpha * hv.z, alpha * hv.w);
    red_add_v4(out + (long)d * HD + lane * 4, m);
}

// ---------------- 6. exact GELU in place -------------------------------------
__global__ void gelu_kernel(float4* out) {
    int i = blockIdx.x * blockDim.x + threadIdx.x;
    if (i >= N_NODES * (HD / 4)) return;
    float4 v = out[i];
    const float r = 0.70710678118654752f;
    v.x = 0.5f * v.x * (1.f + erff(v.x * r));
    v.y = 0.5f * v.y * (1.f + erff(v.y * r));
    v.z = 0.5f * v.z * (1.f + erff(v.z * r));
    v.w = 0.5f * v.w * (1.f + erff(v.w * r));
    out[i] = v;
}

// ---------------- launch -----------------------------------------------------
extern "C" void kernel_launch(void* const* d_in, const int* in_sizes, int n_in,
                              void* d_out, int out_size) {
    const float* x     = (const float*)d_in[0];
    const int*   idx   = (const int*)d_in[1];     // int64 downcast to int32 by harness
    const float* wts   = (const float*)d_in[2];
    const float* W     = (const float*)d_in[3];
    const float* a_src = (const float*)d_in[4];
    const float* a_dst = (const float*)d_in[5];
    float* out = (float*)d_out;

    gemm_kernel<<<(N_NODES + 63) / 64, 256>>>(x, W);
    scores_kernel<<<(N_NODES * 32 + 255) / 256, 256>>>(a_src, a_dst);
    zero_out_kernel<<<(N_NODES * 32 + 255) / 256, 256>>>((float4*)out);
    edge_score_kernel<<<(N_EDGES + 255) / 256, 256>>>(idx, wts);
    aggregate_kernel<<<(N_EDGES * 32 + 255) / 256, 256>>>(idx, out);
    gelu_kernel<<<(N_NODES * 32 + 255) / 256, 256>>>((float4*)out);
}

// round 3
// speedup vs baseline: 1.2427x; 1.2427x over previous
#include <cuda_runtime.h>
#include <cuda_bf16.h>

constexpr int N_NODES = 50000;
constexpr int N_EDGES = 1600000;
constexpr int IN_DIM  = 256;
constexpr int HD      = 128;   // HEADS * OUT_DIM

// ---------------- scratch (static device globals) ----------------------------
__device__ float4 g_h[N_NODES * (HD / 4)];   // h[n,:] as 32 float4/node (25.6 MB)
__device__ float4 g_ssrc[N_NODES];           // per-node src scores (4 heads)
__device__ float4 g_sdst[N_NODES];           // per-node dst scores (4 heads)
__device__ float4 g_csr_ex[N_EDGES];         // exp(e) in CSR(dst) order (25.6 MB)
__device__ int    g_csr_src[N_EDGES];        // src node in CSR(dst) order
__device__ int    g_count[N_NODES];          // in-degree histogram
__device__ int    g_start[N_NODES + 1];      // CSR segment offsets
__device__ int    g_cursor[N_NODES];         // scatter cursors

// ---------------- 1. GEMM: h = x @ W^T  (128x128x16, 8x8 microtile) ----------
__global__ __launch_bounds__(256) void gemm_kernel(const float* __restrict__ x,
                                                   const float* __restrict__ W) {
    __shared__ float As[16][128 + 4];   // [k][m] (node rows)
    __shared__ float Bs[16][128 + 4];   // [k][n] (out dims)

    const int tid = threadIdx.x;
    const int tx = tid & 15;        // n-group (x8)
    const int ty = tid >> 4;        // m-group (x8)
    const int mBase = blockIdx.x * 128;

    const int lr = tid >> 2;        // 0..63
    const int lc = (tid & 3) << 2;  // 0,4,8,12

    float acc[8][8];
#pragma unroll
    for (int i = 0; i < 8; i++)
#pragma unroll
        for (int j = 0; j < 8; j++) acc[i][j] = 0.f;

    for (int k0 = 0; k0 < IN_DIM; k0 += 16) {
#pragma unroll
        for (int it = 0; it < 2; it++) {
            int r = lr + it * 64;
            int row = mBase + r;
            float4 v = make_float4(0.f, 0.f, 0.f, 0.f);
            if (row < N_NODES)
                v = *reinterpret_cast<const float4*>(&x[(long)row * IN_DIM + k0 + lc]);
            As[lc + 0][r] = v.x; As[lc + 1][r] = v.y;
            As[lc + 2][r] = v.z; As[lc + 3][r] = v.w;
        }
#pragma unroll
        for (int it = 0; it < 2; it++) {
            int r = lr + it * 64;   // W rows 0..127, always in bounds
            float4 v = *reinterpret_cast<const float4*>(&W[(long)r * IN_DIM + k0 + lc]);
            Bs[lc + 0][r] = v.x; Bs[lc + 1][r] = v.y;
            Bs[lc + 2][r] = v.z; Bs[lc + 3][r] = v.w;
        }
        __syncthreads();

#pragma unroll
        for (int k = 0; k < 16; k++) {
            float4 a0 = *reinterpret_cast<const float4*>(&As[k][ty * 8]);
            float4 a1 = *reinterpret_cast<const float4*>(&As[k][ty * 8 + 4]);
            float4 b0 = *reinterpret_cast<const float4*>(&Bs[k][tx * 8]);
            float4 b1 = *reinterpret_cast<const float4*>(&Bs[k][tx * 8 + 4]);
            float av[8] = {a0.x, a0.y, a0.z, a0.w, a1.x, a1.y, a1.z, a1.w};
            float bv[8] = {b0.x, b0.y, b0.z, b0.w, b1.x, b1.y, b1.z, b1.w};
#pragma unroll
            for (int i = 0; i < 8; i++)
#pragma unroll
                for (int j = 0; j < 8; j++) acc[i][j] += av[i] * bv[j];
        }
        __syncthreads();
    }

#pragma unroll
    for (int i = 0; i < 8; i++) {
        int row = mBase + ty * 8 + i;
        if (row < N_NODES) {
            g_h[row * 32 + tx * 2 + 0] =
                make_float4(acc[i][0], acc[i][1], acc[i][2], acc[i][3]);
            g_h[row * 32 + tx * 2 + 1] =
                make_float4(acc[i][4], acc[i][5], acc[i][6], acc[i][7]);
        }
    }
}

// ---------------- 2. per-node attention scores (warp per node) ---------------
__global__ __launch_bounds__(256) void scores_kernel(const float* __restrict__ a_src,
                                                     const float* __restrict__ a_dst) {
    int warp = (blockIdx.x * blockDim.x + threadIdx.x) >> 5;
    if (warp >= N_NODES) return;
    int lane = threadIdx.x & 31;
    int head = lane >> 3;
    int sub  = lane & 7;

    float4 hv = g_h[warp * 32 + lane];
    const float4* as4 = reinterpret_cast<const float4*>(a_src);
    const float4* ad4 = reinterpret_cast<const float4*>(a_dst);
    float4 av = as4[head * 8 + sub];
    float4 dv = ad4[head * 8 + sub];

    float ps = hv.x * av.x + hv.y * av.y + hv.z * av.z + hv.w * av.w;
    float pd = hv.x * dv.x + hv.y * dv.y + hv.z * dv.z + hv.w * dv.w;
#pragma unroll
    for (int o = 4; o >= 1; o >>= 1) {
        ps += __shfl_xor_sync(0xffffffffu, ps, o);
        pd += __shfl_xor_sync(0xffffffffu, pd, o);
    }
    if (sub == 0) {
        reinterpret_cast<float*>(&g_ssrc[warp])[head] = ps;
        reinterpret_cast<float*>(&g_sdst[warp])[head] = pd;
    }
    if (lane == 0) g_count[warp] = 0;
}

// ---------------- 3. in-degree histogram -------------------------------------
__global__ __launch_bounds__(256) void count_kernel(const int* __restrict__ idx) {
    int e = blockIdx.x * blockDim.x + threadIdx.x;
    if (e >= N_EDGES) return;
    int2 p = reinterpret_cast<const int2*>(idx)[e];
    atomicAdd(&g_count[p.y], 1);
}

// ---------------- 4. prefix sum over 50k counts (single block) ---------------
__global__ __launch_bounds__(1024) void scan_kernel() {
    __shared__ int sums[1024];
    const int PER = (N_NODES + 1023) / 1024;   // 49
    int tid = threadIdx.x;
    int base = tid * PER;

    int s = 0;
    for (int i = 0; i < PER; i++) {
        int n = base + i;
        if (n < N_NODES) s += g_count[n];
    }
    sums[tid] = s;
    __syncthreads();
    for (int off = 1; off < 1024; off <<= 1) {
        int v = 0;
        if (tid >= off) v = sums[tid - off];
        __syncthreads();
        if (tid >= off) sums[tid] += v;
        __syncthreads();
    }
    int run = (tid == 0) ? 0 : sums[tid - 1];
    for (int i = 0; i < PER; i++) {
        int n = base + i;
        if (n < N_NODES) {
            g_start[n]  = run;
            g_cursor[n] = run;
            run += g_count[n];
        }
    }
    if (tid == 0) g_start[N_NODES] = N_EDGES;
}

// ---------------- 5. edge scatter: ex + CSR placement ------------------------
// Softmax is shift-invariant and e = tanh(.)*w in (-1,1) is bounded, so the
// reference's segment_max subtraction is mathematically a no-op.
__global__ __launch_bounds__(256) void scatter_kernel(const int* __restrict__ idx,
                                                      const float* __restrict__ wts) {
    int e = blockIdx.x * blockDim.x + threadIdx.x;
    if (e >= N_EDGES) return;
    int2 p = reinterpret_cast<const int2*>(idx)[e];
    int s = p.x, d = p.y;
    float w = wts[e];
    float4 a = g_ssrc[s];
    float4 b = g_sdst[d];
    float4 ex;
    ex.x = expf(tanhf(a.x + b.x) * w);
    ex.y = expf(tanhf(a.y + b.y) * w);
    ex.z = expf(tanhf(a.z + b.z) * w);
    ex.w = expf(tanhf(a.w + b.w) * w);
    int pos = atomicAdd(&g_cursor[d], 1);
    g_csr_ex[pos]  = ex;
    g_csr_src[pos] = s;
}

// ---------------- 6. atomic-free aggregation + fused GELU (warp per dst) -----
__global__ __launch_bounds__(256) void aggregate_kernel(float* __restrict__ out) {
    int d = (blockIdx.x * blockDim.x + threadIdx.x) >> 5;
    if (d >= N_NODES) return;
    int lane = threadIdx.x & 31;

    int start = g_start[d];
    int end   = g_start[d + 1];

    const float* exf = reinterpret_cast<const float*>(g_csr_ex);

    // Phase 1: denom per head. lane -> (edge_sub = lane>>2, head = lane&3),
    // 8 edges per iteration, fully coalesced 128B reads of the ex stream.
    int head = lane & 3;
    int esub = lane >> 2;
    float dsum = 0.f;
    for (int e = start + esub; e < end; e += 8)
        dsum += exf[e * 4 + head];
    dsum += __shfl_xor_sync(0xffffffffu, dsum, 4);
    dsum += __shfl_xor_sync(0xffffffffu, dsum, 8);
    dsum += __shfl_xor_sync(0xffffffffu, dsum, 16);
    // lanes 0..3 now hold complete denoms for heads 0..3
    int h2 = lane >> 3;                                   // head owning my out cols
    float inv = 1.f / __shfl_sync(0xffffffffu, dsum, h2);

    // Phase 2: gather h[src], accumulate in registers.
    float4 acc = make_float4(0.f, 0.f, 0.f, 0.f);
#pragma unroll 4
    for (int e = start; e < end; e++) {
        int src = __ldg(&g_csr_src[e]);                   // warp-uniform broadcast
        float alpha = exf[e * 4 + h2] * inv;
        float4 hv = g_h[src * 32 + lane];
        acc.x += alpha * hv.x; acc.y += alpha * hv.y;
        acc.z += alpha * hv.z; acc.w += alpha * hv.w;
    }

    // Fused exact GELU + single store (no atomics, no zero pass).
    const float r = 0.70710678118654752f;
    float4 v;
    v.x = 0.5f * acc.x * (1.f + erff(acc.x * r));
    v.y = 0.5f * acc.y * (1.f + erff(acc.y * r));
    v.z = 0.5f * acc.z * (1.f + erff(acc.z * r));
    v.w = 0.5f * acc.w * (1.f + erff(acc.w * r));
    reinterpret_cast<float4*>(out)[d * 32 + lane] = v;
}

// ---------------- launch -----------------------------------------------------
extern "C" void kernel_launch(void* const* d_in, const int* in_sizes, int n_in,
                              void* d_out, int out_size) {
    const float* x     = (const float*)d_in[0];
    const int*   idx   = (const int*)d_in[1];     // int64 stored as int32 pairs
    const float* wts   = (const float*)d_in[2];
    const float* W     = (const float*)d_in[3];
    const float* a_src = (const float*)d_in[4];
    const float* a_dst = (const float*)d_in[5];
    float* out = (float*)d_out;

    gemm_kernel<<<(N_NODES + 127) / 128, 256>>>(x, W);
    scores_kernel<<<(N_NODES * 32 + 255) / 256, 256>>>(a_src, a_dst);
    count_kernel<<<(N_EDGES + 255) / 256, 256>>>(idx);
    scan_kernel<<<1, 1024>>>();
    scatter_kernel<<<(N_EDGES + 255) / 256, 256>>>(idx, wts);
    aggregate_kernel<<<(N_NODES * 32 + 255) / 256, 256>>>(out);
}

// round 4
// speedup vs baseline: 1.6422x; 1.3215x over previous
#include <cuda_runtime.h>
#include <cuda_bf16.h>

constexpr int N_NODES = 50000;
constexpr int N_EDGES = 1600000;
constexpr int IN_DIM  = 256;
constexpr int HD      = 128;   // HEADS * OUT_DIM

constexpr int SCAN_BLK  = 1024;
constexpr int SCAN_NBLK = (N_NODES + SCAN_BLK - 1) / SCAN_BLK;   // 49

// ---------------- scratch (static device globals) ----------------------------
__device__ float4 g_h[N_NODES * (HD / 4)];   // h[n,:] as 32 float4/node (25.6 MB)
__device__ float4 g_ssrc[N_NODES];           // per-node src scores (4 heads)
__device__ float4 g_sdst[N_NODES];           // per-node dst scores (4 heads)
__device__ float4 g_csr_ex[N_EDGES];         // exp(e) in CSR(dst) order (25.6 MB)
__device__ int    g_csr_src[N_EDGES];        // src node in CSR(dst) order
__device__ int    g_count[N_NODES];          // in-degree histogram
__device__ int    g_start[N_NODES + 1];      // CSR segment offsets
__device__ int    g_cursor[N_NODES];         // scatter cursors
__device__ int    g_blocksum[SCAN_NBLK];     // per-scan-block totals

// ---------------- 1. GEMM: h = x @ W^T  (128x128x16, 8x8 microtile) ----------
__global__ __launch_bounds__(256) void gemm_kernel(const float* __restrict__ x,
                                                   const float* __restrict__ W) {
    __shared__ float As[16][128 + 4];   // [k][m] (node rows)
    __shared__ float Bs[16][128 + 4];   // [k][n] (out dims)

    const int tid = threadIdx.x;
    const int tx = tid & 15;        // n-group (x8)
    const int ty = tid >> 4;        // m-group (x8)
    const int mBase = blockIdx.x * 128;

    const int lr = tid >> 2;        // 0..63
    const int lc = (tid & 3) << 2;  // 0,4,8,12

    float acc[8][8];
#pragma unroll
    for (int i = 0; i < 8; i++)
#pragma unroll
        for (int j = 0; j < 8; j++) acc[i][j] = 0.f;

    for (int k0 = 0; k0 < IN_DIM; k0 += 16) {
#pragma unroll
        for (int it = 0; it < 2; it++) {
            int r = lr + it * 64;
            int row = mBase + r;
            float4 v = make_float4(0.f, 0.f, 0.f, 0.f);
            if (row < N_NODES)
                v = *reinterpret_cast<const float4*>(&x[(long)row * IN_DIM + k0 + lc]);
            As[lc + 0][r] = v.x; As[lc + 1][r] = v.y;
            As[lc + 2][r] = v.z; As[lc + 3][r] = v.w;
        }
#pragma unroll
        for (int it = 0; it < 2; it++) {
            int r = lr + it * 64;   // W rows 0..127, always in bounds
            float4 v = *reinterpret_cast<const float4*>(&W[(long)r * IN_DIM + k0 + lc]);
            Bs[lc + 0][r] = v.x; Bs[lc + 1][r] = v.y;
            Bs[lc + 2][r] = v.z; Bs[lc + 3][r] = v.w;
        }
        __syncthreads();

#pragma unroll
        for (int k = 0; k < 16; k++) {
            float4 a0 = *reinterpret_cast<const float4*>(&As[k][ty * 8]);
            float4 a1 = *reinterpret_cast<const float4*>(&As[k][ty * 8 + 4]);
            float4 b0 = *reinterpret_cast<const float4*>(&Bs[k][tx * 8]);
            float4 b1 = *reinterpret_cast<const float4*>(&Bs[k][tx * 8 + 4]);
            float av[8] = {a0.x, a0.y, a0.z, a0.w, a1.x, a1.y, a1.z, a1.w};
            float bv[8] = {b0.x, b0.y, b0.z, b0.w, b1.x, b1.y, b1.z, b1.w};
#pragma unroll
            for (int i = 0; i < 8; i++)
#pragma unroll
                for (int j = 0; j < 8; j++) acc[i][j] += av[i] * bv[j];
        }
        __syncthreads();
    }

#pragma unroll
    for (int i = 0; i < 8; i++) {
        int row = mBase + ty * 8 + i;
        if (row < N_NODES) {
            g_h[row * 32 + tx * 2 + 0] =
                make_float4(acc[i][0], acc[i][1], acc[i][2], acc[i][3]);
            g_h[row * 32 + tx * 2 + 1] =
                make_float4(acc[i][4], acc[i][5], acc[i][6], acc[i][7]);
        }
    }
}

// ---------------- 2. per-node attention scores (warp per node) ---------------
__global__ __launch_bounds__(256) void scores_kernel(const float* __restrict__ a_src,
                                                     const float* __restrict__ a_dst) {
    int warp = (blockIdx.x * blockDim.x + threadIdx.x) >> 5;
    if (warp >= N_NODES) return;
    int lane = threadIdx.x & 31;
    int head = lane >> 3;
    int sub  = lane & 7;

    float4 hv = g_h[warp * 32 + lane];
    const float4* as4 = reinterpret_cast<const float4*>(a_src);
    const float4* ad4 = reinterpret_cast<const float4*>(a_dst);
    float4 av = as4[head * 8 + sub];
    float4 dv = ad4[head * 8 + sub];

    float ps = hv.x * av.x + hv.y * av.y + hv.z * av.z + hv.w * av.w;
    float pd = hv.x * dv.x + hv.y * dv.y + hv.z * dv.z + hv.w * dv.w;
#pragma unroll
    for (int o = 4; o >= 1; o >>= 1) {
        ps += __shfl_xor_sync(0xffffffffu, ps, o);
        pd += __shfl_xor_sync(0xffffffffu, pd, o);
    }
    if (sub == 0) {
        reinterpret_cast<float*>(&g_ssrc[warp])[head] = ps;
        reinterpret_cast<float*>(&g_sdst[warp])[head] = pd;
    }
    if (lane == 0) g_count[warp] = 0;
}

// ---------------- 3. in-degree histogram -------------------------------------
__global__ __launch_bounds__(256) void count_kernel(const int* __restrict__ idx) {
    int e = blockIdx.x * blockDim.x + threadIdx.x;
    if (e >= N_EDGES) return;
    int2 p = reinterpret_cast<const int2*>(idx)[e];
    atomicAdd(&g_count[p.y], 1);
}

// ---------------- 4. hierarchical prefix sum (3 tiny stages) -----------------
// Stage A: per-block (1024 nodes) exclusive scan + block totals.
__global__ __launch_bounds__(SCAN_BLK) void scan_blocks_kernel() {
    __shared__ int sh[SCAN_BLK];
    int tid = threadIdx.x;
    int n = blockIdx.x * SCAN_BLK + tid;
    int v = (n < N_NODES) ? g_count[n] : 0;
    sh[tid] = v;
    __syncthreads();
#pragma unroll
    for (int off = 1; off < SCAN_BLK; off <<= 1) {
        int t = (tid >= off) ? sh[tid - off] : 0;
        __syncthreads();
        sh[tid] += t;
        __syncthreads();
    }
    if (n < N_NODES) g_start[n] = sh[tid] - v;       // exclusive within block
    if (tid == SCAN_BLK - 1) g_blocksum[blockIdx.x] = sh[tid];
}

// Stage B: scan the 49 block totals (single warp pair).
__global__ __launch_bounds__(64) void scan_tops_kernel() {
    __shared__ int sh[64];
    int tid = threadIdx.x;
    int v = (tid < SCAN_NBLK) ? g_blocksum[tid] : 0;
    sh[tid] = v;
    __syncthreads();
#pragma unroll
    for (int off = 1; off < 64; off <<= 1) {
        int t = (tid >= off) ? sh[tid - off] : 0;
        __syncthreads();
        sh[tid] += t;
        __syncthreads();
    }
    if (tid < SCAN_NBLK) g_blocksum[tid] = sh[tid] - v;   // exclusive block offset
}

// Stage C: apply block offsets, init cursors.
__global__ __launch_bounds__(SCAN_BLK) void scan_apply_kernel() {
    int n = blockIdx.x * SCAN_BLK + threadIdx.x;
    if (n >= N_NODES) return;
    int s = g_start[n] + g_blocksum[blockIdx.x];
    g_start[n]  = s;
    g_cursor[n] = s;
    if (n == 0) g_start[N_NODES] = N_EDGES;
}

// ---------------- 5. edge scatter: ex + CSR placement ------------------------
// Softmax is shift-invariant and e = tanh(.)*w in (-1,1) is bounded, so the
// reference's segment_max subtraction is mathematically a no-op.
__global__ __launch_bounds__(256) void scatter_kernel(const int* __restrict__ idx,
                                                      const float* __restrict__ wts) {
    int e = blockIdx.x * blockDim.x + threadIdx.x;
    if (e >= N_EDGES) return;
    int2 p = reinterpret_cast<const int2*>(idx)[e];
    int s = p.x, d = p.y;
    float w = wts[e];
    float4 a = g_ssrc[s];
    float4 b = g_sdst[d];
    float4 ex;
    ex.x = expf(tanhf(a.x + b.x) * w);
    ex.y = expf(tanhf(a.y + b.y) * w);
    ex.z = expf(tanhf(a.z + b.z) * w);
    ex.w = expf(tanhf(a.w + b.w) * w);
    int pos = atomicAdd(&g_cursor[d], 1);
    g_csr_ex[pos]  = ex;
    g_csr_src[pos] = s;
}

// ---------------- 6. atomic-free aggregation + fused GELU (warp per dst) -----
__global__ __launch_bounds__(256) void aggregate_kernel(float* __restrict__ out) {
    int d = (blockIdx.x * blockDim.x + threadIdx.x) >> 5;
    if (d >= N_NODES) return;
    int lane = threadIdx.x & 31;

    int start = g_start[d];
    int end   = g_start[d + 1];

    const float* exf = reinterpret_cast<const float*>(g_csr_ex);

    // Phase 1: denom per head. lane -> (edge_sub = lane>>2, head = lane&3),
    // 8 edges per iteration, fully coalesced 128B reads of the ex stream.
    int head = lane & 3;
    int esub = lane >> 2;
    float dsum = 0.f;
    for (int e = start + esub; e < end; e += 8)
        dsum += exf[e * 4 + head];
    dsum += __shfl_xor_sync(0xffffffffu, dsum, 4);
    dsum += __shfl_xor_sync(0xffffffffu, dsum, 8);
    dsum += __shfl_xor_sync(0xffffffffu, dsum, 16);
    // lanes 0..3 now hold complete denoms for heads 0..3
    int h2 = lane >> 3;                                   // head owning my out cols
    float inv = 1.f / __shfl_sync(0xffffffffu, dsum, h2);

    // Phase 2: gather h[src], accumulate in registers.
    float4 acc = make_float4(0.f, 0.f, 0.f, 0.f);
#pragma unroll 4
    for (int e = start; e < end; e++) {
        int src = __ldg(&g_csr_src[e]);                   // warp-uniform broadcast
        float alpha = exf[e * 4 + h2] * inv;
        float4 hv = g_h[src * 32 + lane];
        acc.x += alpha * hv.x; acc.y += alpha * hv.y;
        acc.z += alpha * hv.z; acc.w += alpha * hv.w;
    }

    // Fused exact GELU + single store (no atomics, no zero pass).
    const float r = 0.70710678118654752f;
    float4 v;
    v.x = 0.5f * acc.x * (1.f + erff(acc.x * r));
    v.y = 0.5f * acc.y * (1.f + erff(acc.y * r));
    v.z = 0.5f * acc.z * (1.f + erff(acc.z * r));
    v.w = 0.5f * acc.w * (1.f + erff(acc.w * r));
    reinterpret_cast<float4*>(out)[d * 32 + lane] = v;
}

// ---------------- launch -----------------------------------------------------
extern "C" void kernel_launch(void* const* d_in, const int* in_sizes, int n_in,
                              void* d_out, int out_size) {
    const float* x     = (const float*)d_in[0];
    const int*   idx   = (const int*)d_in[1];     // int64 stored as int32 pairs
    const float* wts   = (const float*)d_in[2];
    const float* W     = (const float*)d_in[3];
    const float* a_src = (const float*)d_in[4];
    const float* a_dst = (const float*)d_in[5];
    float* out = (float*)d_out;

    gemm_kernel<<<(N_NODES + 127) / 128, 256>>>(x, W);
    scores_kernel<<<(N_NODES * 32 + 255) / 256, 256>>>(a_src, a_dst);
    count_kernel<<<(N_EDGES + 255) / 256, 256>>>(idx);
    scan_blocks_kernel<<<SCAN_NBLK, SCAN_BLK>>>();
    scan_tops_kernel<<<1, 64>>>();
    scan_apply_kernel<<<SCAN_NBLK, SCAN_BLK>>>();
    scatter_kernel<<<(N_EDGES + 255) / 256, 256>>>(idx, wts);
    aggregate_kernel<<<(N_NODES * 32 + 255) / 256, 256>>>(out);
}

// round 6
// speedup vs baseline: 1.6642x; 1.0134x over previous
#include <cuda_runtime.h>
#include <cuda_fp16.h>

constexpr int N_NODES = 50000;
constexpr int N_EDGES = 1600000;
constexpr int IN_DIM  = 256;
constexpr int HD      = 128;   // HEADS * OUT_DIM

constexpr int SCAN_BLK  = 1024;
constexpr int SCAN_NBLK = (N_NODES + SCAN_BLK - 1) / SCAN_BLK;   // 49

// ---------------- scratch (static device globals) ----------------------------
__device__ float4 g_h[N_NODES * (HD / 4)];   // h fp32 (25.6 MB) — scores use this
__device__ uint4  g_hh[N_NODES * (HD / 8)];  // h fp16 packed (12.8 MB) — gather copy
__device__ float4 g_ssrc[N_NODES];           // per-node src scores (4 heads)
__device__ float4 g_sdst[N_NODES];           // per-node dst scores (4 heads)
__device__ float4 g_csr_ex[N_EDGES];         // exp(e) in CSR(dst) order (25.6 MB)
__device__ int    g_csr_src[N_EDGES];        // src node in CSR(dst) order
__device__ int    g_count[N_NODES];          // in-degree histogram
__device__ int    g_start[N_NODES + 1];      // CSR segment offsets
__device__ int    g_cursor[N_NODES];         // scatter cursors
__device__ int    g_blocksum[SCAN_NBLK];     // per-scan-block totals

// bit-reinterpret helpers (the intrinsics __half2_as_uint etc. don't exist)
__device__ __forceinline__ unsigned pack_h2(float a, float b) {
    __half2 h = __float22half2_rn(make_float2(a, b));
    return *reinterpret_cast<unsigned*>(&h);
}
__device__ __forceinline__ float2 unpack_h2(unsigned u) {
    __half2 h = *reinterpret_cast<__half2*>(&u);
    return __half22float2(h);
}

// ---------------- 0. zero counters -------------------------------------------
__global__ __launch_bounds__(SCAN_BLK) void zero_count_kernel() {
    int n = blockIdx.x * SCAN_BLK + threadIdx.x;
    if (n < N_NODES) g_count[n] = 0;
}

// ---------------- 1. in-degree histogram (only needs idx) --------------------
__global__ __launch_bounds__(256) void count_kernel(const int* __restrict__ idx) {
    int e = blockIdx.x * blockDim.x + threadIdx.x;
    if (e >= N_EDGES) return;
    int2 p = reinterpret_cast<const int2*>(idx)[e];
    atomicAdd(&g_count[p.y], 1);
}

// ---------------- 2. hierarchical prefix sum (3 tiny stages) -----------------
__global__ __launch_bounds__(SCAN_BLK) void scan_blocks_kernel() {
    __shared__ int sh[SCAN_BLK];
    int tid = threadIdx.x;
    int n = blockIdx.x * SCAN_BLK + tid;
    int v = (n < N_NODES) ? g_count[n] : 0;
    sh[tid] = v;
    __syncthreads();
#pragma unroll
    for (int off = 1; off < SCAN_BLK; off <<= 1) {
        int t = (tid >= off) ? sh[tid - off] : 0;
        __syncthreads();
        sh[tid] += t;
        __syncthreads();
    }
    if (n < N_NODES) g_start[n] = sh[tid] - v;       // exclusive within block
    if (tid == SCAN_BLK - 1) g_blocksum[blockIdx.x] = sh[tid];
}

__global__ __launch_bounds__(64) void scan_tops_kernel() {
    __shared__ int sh[64];
    int tid = threadIdx.x;
    int v = (tid < SCAN_NBLK) ? g_blocksum[tid] : 0;
    sh[tid] = v;
    __syncthreads();
#pragma unroll
    for (int off = 1; off < 64; off <<= 1) {
        int t = (tid >= off) ? sh[tid - off] : 0;
        __syncthreads();
        sh[tid] += t;
        __syncthreads();
    }
    if (tid < SCAN_NBLK) g_blocksum[tid] = sh[tid] - v;   // exclusive block offset
}

__global__ __launch_bounds__(SCAN_BLK) void scan_apply_kernel() {
    int n = blockIdx.x * SCAN_BLK + threadIdx.x;
    if (n >= N_NODES) return;
    int s = g_start[n] + g_blocksum[blockIdx.x];
    g_start[n]  = s;
    g_cursor[n] = s;
    if (n == 0) g_start[N_NODES] = N_EDGES;
}

// ---------------- 3. GEMM: h = x @ W^T  (128x128x16, 8x8 microtile) ----------
// Epilogue writes fp32 h (for scores) AND a packed fp16 copy (for aggregation).
__global__ __launch_bounds__(256) void gemm_kernel(const float* __restrict__ x,
                                                   const float* __restrict__ W) {
    __shared__ float As[16][128 + 4];   // [k][m] (node rows)
    __shared__ float Bs[16][128 + 4];   // [k][n] (out dims)

    const int tid = threadIdx.x;
    const int tx = tid & 15;        // n-group (x8)
    const int ty = tid >> 4;        // m-group (x8)
    const int mBase = blockIdx.x * 128;

    const int lr = tid >> 2;        // 0..63
    const int lc = (tid & 3) << 2;  // 0,4,8,12

    float acc[8][8];
#pragma unroll
    for (int i = 0; i < 8; i++)
#pragma unroll
        for (int j = 0; j < 8; j++) acc[i][j] = 0.f;

    for (int k0 = 0; k0 < IN_DIM; k0 += 16) {
#pragma unroll
        for (int it = 0; it < 2; it++) {
            int r = lr + it * 64;
            int row = mBase + r;
            float4 v = make_float4(0.f, 0.f, 0.f, 0.f);
            if (row < N_NODES)
                v = *reinterpret_cast<const float4*>(&x[(long)row * IN_DIM + k0 + lc]);
            As[lc + 0][r] = v.x; As[lc + 1][r] = v.y;
            As[lc + 2][r] = v.z; As[lc + 3][r] = v.w;
        }
#pragma unroll
        for (int it = 0; it < 2; it++) {
            int r = lr + it * 64;   // W rows 0..127, always in bounds
            float4 v = *reinterpret_cast<const float4*>(&W[(long)r * IN_DIM + k0 + lc]);
            Bs[lc + 0][r] = v.x; Bs[lc + 1][r] = v.y;
            Bs[lc + 2][r] = v.z; Bs[lc + 3][r] = v.w;
        }
        __syncthreads();

#pragma unroll
        for (int k = 0; k < 16; k++) {
            float4 a0 = *reinterpret_cast<const float4*>(&As[k][ty * 8]);
            float4 a1 = *reinterpret_cast<const float4*>(&As[k][ty * 8 + 4]);
            float4 b0 = *reinterpret_cast<const float4*>(&Bs[k][tx * 8]);
            float4 b1 = *reinterpret_cast<const float4*>(&Bs[k][tx * 8 + 4]);
            float av[8] = {a0.x, a0.y, a0.z, a0.w, a1.x, a1.y, a1.z, a1.w};
            float bv[8] = {b0.x, b0.y, b0.z, b0.w, b1.x, b1.y, b1.z, b1.w};
#pragma unroll
            for (int i = 0; i < 8; i++)
#pragma unroll
                for (int j = 0; j < 8; j++) acc[i][j] += av[i] * bv[j];
        }
        __syncthreads();
    }

#pragma unroll
    for (int i = 0; i < 8; i++) {
        int row = mBase + ty * 8 + i;
        if (row < N_NODES) {
            g_h[row * 32 + tx * 2 + 0] =
                make_float4(acc[i][0], acc[i][1], acc[i][2], acc[i][3]);
            g_h[row * 32 + tx * 2 + 1] =
                make_float4(acc[i][4], acc[i][5], acc[i][6], acc[i][7]);
            // packed fp16 copy: 8 cols -> 4x half2 -> one uint4
            uint4 pk;
            pk.x = pack_h2(acc[i][0], acc[i][1]);
            pk.y = pack_h2(acc[i][2], acc[i][3]);
            pk.z = pack_h2(acc[i][4], acc[i][5]);
            pk.w = pack_h2(acc[i][6], acc[i][7]);
            g_hh[row * 16 + tx] = pk;
        }
    }
}

// ---------------- 4. per-node attention scores (warp per node) ---------------
__global__ __launch_bounds__(256) void scores_kernel(const float* __restrict__ a_src,
                                                     const float* __restrict__ a_dst) {
    int warp = (blockIdx.x * blockDim.x + threadIdx.x) >> 5;
    if (warp >= N_NODES) return;
    int lane = threadIdx.x & 31;
    int head = lane >> 3;
    int sub  = lane & 7;

    float4 hv = g_h[warp * 32 + lane];
    const float4* as4 = reinterpret_cast<const float4*>(a_src);
    const float4* ad4 = reinterpret_cast<const float4*>(a_dst);
    float4 av = as4[head * 8 + sub];
    float4 dv = ad4[head * 8 + sub];

    float ps = hv.x * av.x + hv.y * av.y + hv.z * av.z + hv.w * av.w;
    float pd = hv.x * dv.x + hv.y * dv.y + hv.z * dv.z + hv.w * dv.w;
#pragma unroll
    for (int o = 4; o >= 1; o >>= 1) {
        ps += __shfl_xor_sync(0xffffffffu, ps, o);
        pd += __shfl_xor_sync(0xffffffffu, pd, o);
    }
    if (sub == 0) {
        reinterpret_cast<float*>(&g_ssrc[warp])[head] = ps;
        reinterpret_cast<float*>(&g_sdst[warp])[head] = pd;
    }
}

// ---------------- 5. edge scatter: ex + CSR placement ------------------------
// Softmax is shift-invariant and e = tanh(.)*w in (-1,1) is bounded, so the
// reference's segment_max subtraction is mathematically a no-op.
__global__ __launch_bounds__(256) void scatter_kernel(const int* __restrict__ idx,
                                                      const float* __restrict__ wts) {
    int e = blockIdx.x * blockDim.x + threadIdx.x;
    if (e >= N_EDGES) return;
    int2 p = reinterpret_cast<const int2*>(idx)[e];
    int s = p.x, d = p.y;
    float w = wts[e];
    float4 a = g_ssrc[s];
    float4 b = g_sdst[d];
    float4 ex;
    ex.x = expf(tanhf(a.x + b.x) * w);
    ex.y = expf(tanhf(a.y + b.y) * w);
    ex.z = expf(tanhf(a.z + b.z) * w);
    ex.w = expf(tanhf(a.w + b.w) * w);
    int pos = atomicAdd(&g_cursor[d], 1);
    g_csr_ex[pos]  = ex;
    g_csr_src[pos] = s;
}

// ---------------- 6. atomic-free aggregation + fused GELU (warp per dst) -----
__global__ __launch_bounds__(256) void aggregate_kernel(float* __restrict__ out) {
    int d = (blockIdx.x * blockDim.x + threadIdx.x) >> 5;
    if (d >= N_NODES) return;
    int lane = threadIdx.x & 31;

    int start = g_start[d];
    int end   = g_start[d + 1];

    const float* exf = reinterpret_cast<const float*>(g_csr_ex);

    // Phase 1: denom per head; 8 edges/iter, coalesced 128B reads.
    int head = lane & 3;
    int esub = lane >> 2;
    float dsum = 0.f;
    for (int e = start + esub; e < end; e += 8)
        dsum += exf[e * 4 + head];
    dsum += __shfl_xor_sync(0xffffffffu, dsum, 4);
    dsum += __shfl_xor_sync(0xffffffffu, dsum, 8);
    dsum += __shfl_xor_sync(0xffffffffu, dsum, 16);
    int h2 = lane >> 3;                                   // head owning my out cols
    float inv = 1.f / __shfl_sync(0xffffffffu, dsum, h2);

    // Phase 2: fp16 gather of h[src] (256B/edge instead of 512B), fp32 math.
    const uint2* hh2 = reinterpret_cast<const uint2*>(g_hh);
    float4 acc = make_float4(0.f, 0.f, 0.f, 0.f);
#pragma unroll 4
    for (int e = start; e < end; e++) {
        int src = __ldg(&g_csr_src[e]);                   // warp-uniform broadcast
        float alpha = exf[e * 4 + h2] * inv;
        uint2 raw = __ldg(&hh2[src * 32 + lane]);         // 4 halfs = dims lane*4..+3
        float2 f01 = unpack_h2(raw.x);
        float2 f23 = unpack_h2(raw.y);
        acc.x += alpha * f01.x; acc.y += alpha * f01.y;
        acc.z += alpha * f23.x; acc.w += alpha * f23.y;
    }

    // Fused exact GELU + single store.
    const float r = 0.70710678118654752f;
    float4 v;
    v.x = 0.5f * acc.x * (1.f + erff(acc.x * r));
    v.y = 0.5f * acc.y * (1.f + erff(acc.y * r));
    v.z = 0.5f * acc.z * (1.f + erff(acc.z * r));
    v.w = 0.5f * acc.w * (1.f + erff(acc.w * r));
    reinterpret_cast<float4*>(out)[d * 32 + lane] = v;
}

// ---------------- launch -----------------------------------------------------
// Order chosen so the ncu-profiled slot lands on gemm_kernel (next opt target).
extern "C" void kernel_launch(void* const* d_in, const int* in_sizes, int n_in,
                              void* d_out, int out_size) {
    const float* x     = (const float*)d_in[0];
    const int*   idx   = (const int*)d_in[1];     // int64 stored as int32 pairs
    const float* wts   = (const float*)d_in[2];
    const float* W     = (const float*)d_in[3];
    const float* a_src = (const float*)d_in[4];
    const float* a_dst = (const float*)d_in[5];
    float* out = (float*)d_out;

    zero_count_kernel<<<SCAN_NBLK, SCAN_BLK>>>();                     // 1
    count_kernel<<<(N_EDGES + 255) / 256, 256>>>(idx);                // 2
    scan_blocks_kernel<<<SCAN_NBLK, SCAN_BLK>>>();                    // 3
    gemm_kernel<<<(N_NODES + 127) / 128, 256>>>(x, W);                // 4 <- profiled
    scan_tops_kernel<<<1, 64>>>();                                    // 5
    scores_kernel<<<(N_NODES * 32 + 255) / 256, 256>>>(a_src, a_dst); // 6
    scan_apply_kernel<<<SCAN_NBLK, SCAN_BLK>>>();                     // 7
    scatter_kernel<<<(N_EDGES + 255) / 256, 256>>>(idx, wts);         // 8
    aggregate_kernel<<<(N_NODES * 32 + 255) / 256, 256>>>(out);       // 9
}

// round 8
// speedup vs baseline: 1.8758x; 1.1272x over previous
#include <cuda_runtime.h>
#include <cuda_fp16.h>
#include <cuda_bf16.h>
#include <cstdint>

constexpr int N_NODES = 50000;
constexpr int N_EDGES = 1600000;
constexpr int IN_DIM  = 256;
constexpr int HD      = 128;   // HEADS * OUT_DIM

constexpr int SCAN_BLK  = 1024;
constexpr int SCAN_NBLK = (N_NODES + SCAN_BLK - 1) / SCAN_BLK;   // 49

constexpr int TILE_M = 128;
constexpr int KC     = 32;                 // bf16 K-chunk
constexpr int KPAD   = 40;                 // smem row stride (conflict-free)

// ---------------- scratch (static device globals) ----------------------------
__device__ float4 g_h[N_NODES * (HD / 4)];   // h fp32 (25.6 MB) — scores use this
__device__ uint4  g_hh[N_NODES * (HD / 8)];  // h fp16 packed (12.8 MB) — gather copy
__device__ float4 g_ssrc[N_NODES];
__device__ float4 g_sdst[N_NODES];
__device__ float4 g_csr_ex[N_EDGES];
__device__ int    g_csr_src[N_EDGES];
__device__ int    g_count[N_NODES];
__device__ int    g_start[N_NODES + 1];
__device__ int    g_cursor[N_NODES];
__device__ int    g_blocksum[SCAN_NBLK];

// ---------------- helpers ----------------------------------------------------
__device__ __forceinline__ unsigned pack_h2(float a, float b) {   // fp16 pair
    __half2 h = __float22half2_rn(make_float2(a, b));
    return *reinterpret_cast<unsigned*>(&h);
}
__device__ __forceinline__ float2 unpack_h2(unsigned u) {
    __half2 h = *reinterpret_cast<__half2*>(&u);
    return __half22float2(h);
}
__device__ __forceinline__ unsigned pack_bf2(__nv_bfloat16 a, __nv_bfloat16 b) {
    __nv_bfloat162 t = __halves2bfloat162(a, b);
    return *reinterpret_cast<unsigned*>(&t);
}
__device__ __forceinline__ uint32_t ld2(const uint16_t* p) {
    return *reinterpret_cast<const uint32_t*>(p);
}
// HMMA bf16: m16n8k16, row.col, fp32 accumulate (baseline PTX, sm_80+)
__device__ __forceinline__ void mma16816(float* d, const uint32_t* a,
                                         uint32_t b0, uint32_t b1) {
    asm volatile(
        "mma.sync.aligned.m16n8k16.row.col.f32.bf16.bf16.f32 "
        "{%0,%1,%2,%3}, {%4,%5,%6,%7}, {%8,%9}, {%0,%1,%2,%3};"
        : "+f"(d[0]), "+f"(d[1]), "+f"(d[2]), "+f"(d[3])
        : "r"(a[0]), "r"(a[1]), "r"(a[2]), "r"(a[3]), "r"(b0), "r"(b1));
}
// split fp32 -> (hi, lo) bf16 pair packs for 4 consecutive values
__device__ __forceinline__ void split4(float4 v, uint2& hi, uint2& lo) {
    __nv_bfloat16 h0 = __float2bfloat16_rn(v.x);
    __nv_bfloat16 h1 = __float2bfloat16_rn(v.y);
    __nv_bfloat16 h2 = __float2bfloat16_rn(v.z);
    __nv_bfloat16 h3 = __float2bfloat16_rn(v.w);
    hi = make_uint2(pack_bf2(h0, h1), pack_bf2(h2, h3));
    lo = make_uint2(pack_bf2(__float2bfloat16_rn(v.x - __bfloat162float(h0)),
                             __float2bfloat16_rn(v.y - __bfloat162float(h1))),
                    pack_bf2(__float2bfloat16_rn(v.z - __bfloat162float(h2)),
                             __float2bfloat16_rn(v.w - __bfloat162float(h3))));
}

// ---------------- 0-2: counters + histogram + hierarchical scan --------------
__global__ __launch_bounds__(SCAN_BLK) void zero_count_kernel() {
    int n = blockIdx.x * SCAN_BLK + threadIdx.x;
    if (n < N_NODES) g_count[n] = 0;
}
__global__ __launch_bounds__(256) void count_kernel(const int* __restrict__ idx) {
    int e = blockIdx.x * blockDim.x + threadIdx.x;
    if (e >= N_EDGES) return;
    int2 p = reinterpret_cast<const int2*>(idx)[e];
    atomicAdd(&g_count[p.y], 1);
}
__global__ __launch_bounds__(SCAN_BLK) void scan_blocks_kernel() {
    __shared__ int sh[SCAN_BLK];
    int tid = threadIdx.x;
    int n = blockIdx.x * SCAN_BLK + tid;
    int v = (n < N_NODES) ? g_count[n] : 0;
    sh[tid] = v;
    __syncthreads();
#pragma unroll
    for (int off = 1; off < SCAN_BLK; off <<= 1) {
        int t = (tid >= off) ? sh[tid - off] : 0;
        __syncthreads();
        sh[tid] += t;
        __syncthreads();
    }
    if (n < N_NODES) g_start[n] = sh[tid] - v;
    if (tid == SCAN_BLK - 1) g_blocksum[blockIdx.x] = sh[tid];
}
__global__ __launch_bounds__(64) void scan_tops_kernel() {
    __shared__ int sh[64];
    int tid = threadIdx.x;
    int v = (tid < SCAN_NBLK) ? g_blocksum[tid] : 0;
    sh[tid] = v;
    __syncthreads();
#pragma unroll
    for (int off = 1; off < 64; off <<= 1) {
        int t = (tid >= off) ? sh[tid - off] : 0;
        __syncthreads();
        sh[tid] += t;
        __syncthreads();
    }
    if (tid < SCAN_NBLK) g_blocksum[tid] = sh[tid] - v;
}
__global__ __launch_bounds__(SCAN_BLK) void scan_apply_kernel() {
    int n = blockIdx.x * SCAN_BLK + threadIdx.x;
    if (n >= N_NODES) return;
    int s = g_start[n] + g_blocksum[blockIdx.x];
    g_start[n]  = s;
    g_cursor[n] = s;
    if (n == 0) g_start[N_NODES] = N_EDGES;
}

// ---------------- 3. HMMA bf16-split GEMM: h = x @ W^T -----------------------
// h = x_hi*W_hi + x_hi*W_lo + x_lo*W_hi (fp32 acc); lo*lo term ~2^-18, dropped.
// 8 warps as 4(m) x 2(n); warp tile 32x64 = 2x8 m16n8k16 fragments.
__global__ __launch_bounds__(256) void gemm_hmma_kernel(const float* __restrict__ x,
                                                        const float* __restrict__ W) {
    __shared__ uint16_t XH[TILE_M][KPAD];
    __shared__ uint16_t XL[TILE_M][KPAD];
    __shared__ uint16_t WH[HD][KPAD];
    __shared__ uint16_t WL[HD][KPAD];

    const int tid  = threadIdx.x;
    const int wid  = tid >> 5;
    const int lane = tid & 31;
    const int warp_m = wid >> 1;        // 0..3 -> rows 32*warp_m
    const int warp_n = wid & 1;         // 0..1 -> cols 64*warp_n
    const int mBase = blockIdx.x * TILE_M;

    const int qr = lane >> 2;           // 0..7
    const int qc = (lane & 3) * 2;      // 0,2,4,6

    float d[2][8][4];
#pragma unroll
    for (int i = 0; i < 2; i++)
#pragma unroll
        for (int j = 0; j < 8; j++)
#pragma unroll
            for (int t = 0; t < 4; t++) d[i][j][t] = 0.f;

    for (int c = 0; c < IN_DIM / KC; c++) {
        const int k0 = c * KC;
        // ---- load + split into smem: 128 rows x 32 cols each for x and W ----
#pragma unroll
        for (int it = 0; it < 4; it++) {
            int i   = it * 256 + tid;   // 1024 float4 slots
            int row = i >> 3;
            int c4  = (i & 7) * 4;      // col in floats
            float4 v = make_float4(0.f, 0.f, 0.f, 0.f);
            int grow = mBase + row;
            if (grow < N_NODES)
                v = *reinterpret_cast<const float4*>(&x[(long)grow * IN_DIM + k0 + c4]);
            uint2 hi, lo;
            split4(v, hi, lo);
            *reinterpret_cast<uint2*>(&XH[row][c4]) = hi;
            *reinterpret_cast<uint2*>(&XL[row][c4]) = lo;
            float4 w = *reinterpret_cast<const float4*>(&W[(long)row * IN_DIM + k0 + c4]);
            split4(w, hi, lo);
            *reinterpret_cast<uint2*>(&WH[row][c4]) = hi;
            *reinterpret_cast<uint2*>(&WL[row][c4]) = lo;
        }
        __syncthreads();

#pragma unroll
        for (int ks = 0; ks < 2; ks++) {
            const int kb = ks * 16 + qc;
            uint32_t a[2][4];
            // --- A = x_hi : multiplies W_hi and W_lo ---
#pragma unroll
            for (int i = 0; i < 2; i++) {
                int r = warp_m * 32 + i * 16 + qr;
                a[i][0] = ld2(&XH[r][kb]);     a[i][1] = ld2(&XH[r + 8][kb]);
                a[i][2] = ld2(&XH[r][kb + 8]); a[i][3] = ld2(&XH[r + 8][kb + 8]);
            }
#pragma unroll
            for (int j = 0; j < 8; j++) {
                int n = warp_n * 64 + j * 8 + qr;
                uint32_t b0 = ld2(&WH[n][kb]), b1 = ld2(&WH[n][kb + 8]);
                mma16816(d[0][j], a[0], b0, b1);
                mma16816(d[1][j], a[1], b0, b1);
                uint32_t c0 = ld2(&WL[n][kb]), c1 = ld2(&WL[n][kb + 8]);
                mma16816(d[0][j], a[0], c0, c1);
                mma16816(d[1][j], a[1], c0, c1);
            }
            // --- A = x_lo : multiplies W_hi ---
#pragma unroll
            for (int i = 0; i < 2; i++) {
                int r = warp_m * 32 + i * 16 + qr;
                a[i][0] = ld2(&XL[r][kb]);     a[i][1] = ld2(&XL[r + 8][kb]);
                a[i][2] = ld2(&XL[r][kb + 8]); a[i][3] = ld2(&XL[r + 8][kb + 8]);
            }
#pragma unroll
            for (int j = 0; j < 8; j++) {
                int n = warp_n * 64 + j * 8 + qr;
                uint32_t b0 = ld2(&WH[n][kb]), b1 = ld2(&WH[n][kb + 8]);
                mma16816(d[0][j], a[0], b0, b1);
                mma16816(d[1][j], a[1], b0, b1);
            }
        }
        __syncthreads();
    }

    // ---- epilogue: fp32 h + packed fp16 copy ----
    float*    hf  = reinterpret_cast<float*>(g_h);
    unsigned* hhu = reinterpret_cast<unsigned*>(g_hh);
#pragma unroll
    for (int i = 0; i < 2; i++) {
        int node0 = mBase + warp_m * 32 + i * 16 + qr;
        int node1 = node0 + 8;
#pragma unroll
        for (int j = 0; j < 8; j++) {
            int col = warp_n * 64 + j * 8 + qc;
            if (node0 < N_NODES) {
                *reinterpret_cast<float2*>(&hf[(long)node0 * HD + col]) =
                    make_float2(d[i][j][0], d[i][j][1]);
                hhu[node0 * 64 + (col >> 1)] = pack_h2(d[i][j][0], d[i][j][1]);
            }
            if (node1 < N_NODES) {
                *reinterpret_cast<float2*>(&hf[(long)node1 * HD + col]) =
                    make_float2(d[i][j][2], d[i][j][3]);
                hhu[node1 * 64 + (col >> 1)] = pack_h2(d[i][j][2], d[i][j][3]);
            }
        }
    }
}

// ---------------- 4. per-node attention scores (warp per node) ---------------
__global__ __launch_bounds__(256) void scores_kernel(const float* __restrict__ a_src,
                                                     const float* __restrict__ a_dst) {
    int warp = (blockIdx.x * blockDim.x + threadIdx.x) >> 5;
    if (warp >= N_NODES) return;
    int lane = threadIdx.x & 31;
    int head = lane >> 3;
    int sub  = lane & 7;

    float4 hv = g_h[warp * 32 + lane];
    const float4* as4 = reinterpret_cast<const float4*>(a_src);
    const float4* ad4 = reinterpret_cast<const float4*>(a_dst);
    float4 av = as4[head * 8 + sub];
    float4 dv = ad4[head * 8 + sub];

    float ps = hv.x * av.x + hv.y * av.y + hv.z * av.z + hv.w * av.w;
    float pd = hv.x * dv.x + hv.y * dv.y + hv.z * dv.z + hv.w * dv.w;
#pragma unroll
    for (int o = 4; o >= 1; o >>= 1) {
        ps += __shfl_xor_sync(0xffffffffu, ps, o);
        pd += __shfl_xor_sync(0xffffffffu, pd, o);
    }
    if (sub == 0) {
        reinterpret_cast<float*>(&g_ssrc[warp])[head] = ps;
        reinterpret_cast<float*>(&g_sdst[warp])[head] = pd;
    }
}

// ---------------- 5. edge scatter: ex + CSR placement ------------------------
// Softmax is shift-invariant and e = tanh(.)*w in (-1,1) is bounded, so the
// reference's segment_max subtraction is mathematically a no-op.
__global__ __launch_bounds__(256) void scatter_kernel(const int* __restrict__ idx,
                                                      const float* __restrict__ wts) {
    int e = blockIdx.x * blockDim.x + threadIdx.x;
    if (e >= N_EDGES) return;
    int2 p = reinterpret_cast<const int2*>(idx)[e];
    int s = p.x, d = p.y;
    float w = wts[e];
    float4 a = g_ssrc[s];
    float4 b = g_sdst[d];
    float4 ex;
    ex.x = expf(tanhf(a.x + b.x) * w);
    ex.y = expf(tanhf(a.y + b.y) * w);
    ex.z = expf(tanhf(a.z + b.z) * w);
    ex.w = expf(tanhf(a.w + b.w) * w);
    int pos = atomicAdd(&g_cursor[d], 1);
    g_csr_ex[pos]  = ex;
    g_csr_src[pos] = s;
}

// ---------------- 6. atomic-free aggregation + fused GELU (warp per dst) -----
__global__ __launch_bounds__(256) void aggregate_kernel(float* __restrict__ out) {
    int d = (blockIdx.x * blockDim.x + threadIdx.x) >> 5;
    if (d >= N_NODES) return;
    int lane = threadIdx.x & 31;

    int start = g_start[d];
    int end   = g_start[d + 1];

    const float* exf = reinterpret_cast<const float*>(g_csr_ex);

    int head = lane & 3;
    int esub = lane >> 2;
    float dsum = 0.f;
    for (int e = start + esub; e < end; e += 8)
        dsum += exf[e * 4 + head];
    dsum += __shfl_xor_sync(0xffffffffu, dsum, 4);
    dsum += __shfl_xor_sync(0xffffffffu, dsum, 8);
    dsum += __shfl_xor_sync(0xffffffffu, dsum, 16);
    int h2 = lane >> 3;
    float inv = 1.f / __shfl_sync(0xffffffffu, dsum, h2);

    const uint2* hh2 = reinterpret_cast<const uint2*>(g_hh);
    float4 acc = make_float4(0.f, 0.f, 0.f, 0.f);
#pragma unroll 4
    for (int e = start; e < end; e++) {
        int src = __ldg(&g_csr_src[e]);
        float alpha = exf[e * 4 + h2] * inv;
        uint2 raw = __ldg(&hh2[src * 32 + lane]);
        float2 f01 = unpack_h2(raw.x);
        float2 f23 = unpack_h2(raw.y);
        acc.x += alpha * f01.x; acc.y += alpha * f01.y;
        acc.z += alpha * f23.x; acc.w += alpha * f23.y;
    }

    const float r = 0.70710678118654752f;
    float4 v;
    v.x = 0.5f * acc.x * (1.f + erff(acc.x * r));
    v.y = 0.5f * acc.y * (1.f + erff(acc.y * r));
    v.z = 0.5f * acc.z * (1.f + erff(acc.z * r));
    v.w = 0.5f * acc.w * (1.f + erff(acc.w * r));
    reinterpret_cast<float4*>(out)[d * 32 + lane] = v;
}

// ---------------- launch -----------------------------------------------------
extern "C" void kernel_launch(void* const* d_in, const int* in_sizes, int n_in,
                              void* d_out, int out_size) {
    const float* x     = (const float*)d_in[0];
    const int*   idx   = (const int*)d_in[1];     // int64 stored as int32 pairs
    const float* wts   = (const float*)d_in[2];
    const float* W     = (const float*)d_in[3];
    const float* a_src = (const float*)d_in[4];
    const float* a_dst = (const float*)d_in[5];
    float* out = (float*)d_out;

    zero_count_kernel<<<SCAN_NBLK, SCAN_BLK>>>();                          // 1
    count_kernel<<<(N_EDGES + 255) / 256, 256>>>(idx);                     // 2
    scan_blocks_kernel<<<SCAN_NBLK, SCAN_BLK>>>();                         // 3
    gemm_hmma_kernel<<<(N_NODES + TILE_M - 1) / TILE_M, 256>>>(x, W);      // 4 <- profiled
    scan_tops_kernel<<<1, 64>>>();                                         // 5
    scores_kernel<<<(N_NODES * 32 + 255) / 256, 256>>>(a_src, a_dst);      // 6
    scan_apply_kernel<<<SCAN_NBLK, SCAN_BLK>>>();                          // 7
    scatter_kernel<<<(N_EDGES + 255) / 256, 256>>>(idx, wts);              // 8
    aggregate_kernel<<<(N_NODES * 32 + 255) / 256, 256>>>(out);            // 9
}

// round 9
// speedup vs baseline: 2.0786x; 1.1081x over previous
#include <cuda_runtime.h>
#include <cuda_fp16.h>
#include <cuda_bf16.h>
#include <cstdint>

constexpr int N_NODES = 50000;
constexpr int N_EDGES = 1600000;
constexpr int IN_DIM  = 256;
constexpr int HD      = 128;   // HEADS * OUT_DIM

constexpr int SCAN_BLK  = 1024;
constexpr int SCAN_NBLK = (N_NODES + SCAN_BLK - 1) / SCAN_BLK;   // 49

constexpr int TILE_M = 128;
constexpr int KC     = 32;                 // bf16 K-chunk
constexpr int KPAD   = 40;                 // smem row stride (conflict-free)
constexpr int NCH    = IN_DIM / KC;        // 8 chunks

// ---------------- scratch (static device globals) ----------------------------
__device__ float4 g_h[N_NODES * (HD / 4)];   // h fp32 (25.6 MB) — scores use this
__device__ uint4  g_hh[N_NODES * (HD / 8)];  // h fp16 packed (12.8 MB) — gather copy
__device__ float4 g_ssrc[N_NODES];
__device__ float4 g_sdst[N_NODES];
__device__ float4 g_csr_ex[N_EDGES];
__device__ int    g_csr_src[N_EDGES];
__device__ int    g_count[N_NODES];
__device__ int    g_start[N_NODES + 1];
__device__ int    g_cursor[N_NODES];
__device__ int    g_blocksum[SCAN_NBLK];

// ---------------- helpers ----------------------------------------------------
__device__ __forceinline__ unsigned pack_h2(float a, float b) {   // fp16 pair
    __half2 h = __float22half2_rn(make_float2(a, b));
    return *reinterpret_cast<unsigned*>(&h);
}
__device__ __forceinline__ float2 unpack_h2(unsigned u) {
    __half2 h = *reinterpret_cast<__half2*>(&u);
    return __half22float2(h);
}
__device__ __forceinline__ unsigned pack_bf2(__nv_bfloat16 a, __nv_bfloat16 b) {
    __nv_bfloat162 t = __halves2bfloat162(a, b);
    return *reinterpret_cast<unsigned*>(&t);
}
__device__ __forceinline__ uint32_t ld2(const uint16_t* p) {
    return *reinterpret_cast<const uint32_t*>(p);
}
// HMMA bf16: m16n8k16, row.col, fp32 accumulate (baseline PTX, sm_80+)
__device__ __forceinline__ void mma16816(float* d, const uint32_t* a,
                                         uint32_t b0, uint32_t b1) {
    asm volatile(
        "mma.sync.aligned.m16n8k16.row.col.f32.bf16.bf16.f32 "
        "{%0,%1,%2,%3}, {%4,%5,%6,%7}, {%8,%9}, {%0,%1,%2,%3};"
        : "+f"(d[0]), "+f"(d[1]), "+f"(d[2]), "+f"(d[3])
        : "r"(a[0]), "r"(a[1]), "r"(a[2]), "r"(a[3]), "r"(b0), "r"(b1));
}
// split fp32 -> (hi, lo) bf16 pair packs for 4 consecutive values
__device__ __forceinline__ void split4(float4 v, uint2& hi, uint2& lo) {
    __nv_bfloat16 h0 = __float2bfloat16_rn(v.x);
    __nv_bfloat16 h1 = __float2bfloat16_rn(v.y);
    __nv_bfloat16 h2 = __float2bfloat16_rn(v.z);
    __nv_bfloat16 h3 = __float2bfloat16_rn(v.w);
    hi = make_uint2(pack_bf2(h0, h1), pack_bf2(h2, h3));
    lo = make_uint2(pack_bf2(__float2bfloat16_rn(v.x - __bfloat162float(h0)),
                             __float2bfloat16_rn(v.y - __bfloat162float(h1))),
                    pack_bf2(__float2bfloat16_rn(v.z - __bfloat162float(h2)),
                             __float2bfloat16_rn(v.w - __bfloat162float(h3))));
}

// ---------------- 0-2: counters + histogram + hierarchical scan --------------
__global__ __launch_bounds__(SCAN_BLK) void zero_count_kernel() {
    int n = blockIdx.x * SCAN_BLK + threadIdx.x;
    if (n < N_NODES) g_count[n] = 0;
}
__global__ __launch_bounds__(256) void count_kernel(const int* __restrict__ idx) {
    int e = blockIdx.x * blockDim.x + threadIdx.x;
    if (e >= N_EDGES) return;
    int2 p = reinterpret_cast<const int2*>(idx)[e];
    atomicAdd(&g_count[p.y], 1);
}
__global__ __launch_bounds__(SCAN_BLK) void scan_blocks_kernel() {
    __shared__ int sh[SCAN_BLK];
    int tid = threadIdx.x;
    int n = blockIdx.x * SCAN_BLK + tid;
    int v = (n < N_NODES) ? g_count[n] : 0;
    sh[tid] = v;
    __syncthreads();
#pragma unroll
    for (int off = 1; off < SCAN_BLK; off <<= 1) {
        int t = (tid >= off) ? sh[tid - off] : 0;
        __syncthreads();
        sh[tid] += t;
        __syncthreads();
    }
    if (n < N_NODES) g_start[n] = sh[tid] - v;
    if (tid == SCAN_BLK - 1) g_blocksum[blockIdx.x] = sh[tid];
}
__global__ __launch_bounds__(64) void scan_tops_kernel() {
    __shared__ int sh[64];
    int tid = threadIdx.x;
    int v = (tid < SCAN_NBLK) ? g_blocksum[tid] : 0;
    sh[tid] = v;
    __syncthreads();
#pragma unroll
    for (int off = 1; off < 64; off <<= 1) {
        int t = (tid >= off) ? sh[tid - off] : 0;
        __syncthreads();
        sh[tid] += t;
        __syncthreads();
    }
    if (tid < SCAN_NBLK) g_blocksum[tid] = sh[tid] - v;
}
__global__ __launch_bounds__(SCAN_BLK) void scan_apply_kernel() {
    int n = blockIdx.x * SCAN_BLK + threadIdx.x;
    if (n >= N_NODES) return;
    int s = g_start[n] + g_blocksum[blockIdx.x];
    g_start[n]  = s;
    g_cursor[n] = s;
    if (n == 0) g_start[N_NODES] = N_EDGES;
}

// ---------------- 3. pipelined HMMA bf16-split GEMM: h = x @ W^T -------------
// h = x_hi*W_hi + x_hi*W_lo + x_lo*W_hi (fp32 acc); lo*lo term ~2^-18, dropped.
// Double-buffered smem + register prefetch: LDGs of chunk c+1 overlap MMA of c.
__global__ __launch_bounds__(256, 1) void gemm_hmma_kernel(const float* __restrict__ x,
                                                           const float* __restrict__ W) {
    __shared__ uint16_t XH[2][TILE_M][KPAD];
    __shared__ uint16_t XL[2][TILE_M][KPAD];
    __shared__ uint16_t WH[2][HD][KPAD];
    __shared__ uint16_t WL[2][HD][KPAD];

    const int tid  = threadIdx.x;
    const int wid  = tid >> 5;
    const int lane = tid & 31;
    const int warp_m = wid >> 1;        // 0..3 -> rows 32*warp_m
    const int warp_n = wid & 1;         // 0..1 -> cols 64*warp_n
    const int mBase = blockIdx.x * TILE_M;

    const int qr = lane >> 2;           // 0..7
    const int qc = (lane & 3) * 2;      // 0,2,4,6

    const int lrow = tid >> 1;          // 0..127: my load row
    const int lc4  = (tid & 1) * 16;    // float col base: 0 or 16
    const int xrow = mBase + lrow;
    const bool xok = (xrow < N_NODES);

    float d[2][8][4];
#pragma unroll
    for (int i = 0; i < 2; i++)
#pragma unroll
        for (int j = 0; j < 8; j++)
#pragma unroll
            for (int t = 0; t < 4; t++) d[i][j][t] = 0.f;

    float4 xv[4], wv[4];
    // prologue: load chunk 0 (each thread: 4 float4 of x-row, 4 of W-row)
#pragma unroll
    for (int q = 0; q < 4; q++) {
        xv[q] = xok ? *reinterpret_cast<const float4*>(&x[(long)xrow * IN_DIM + lc4 + q * 4])
                    : make_float4(0.f, 0.f, 0.f, 0.f);
        wv[q] = *reinterpret_cast<const float4*>(&W[(long)lrow * IN_DIM + lc4 + q * 4]);
    }

    for (int c = 0; c < NCH; c++) {
        const int b = c & 1;
        // ---- convert prefetched regs -> smem buffer b ----
#pragma unroll
        for (int q = 0; q < 4; q++) {
            int col = lc4 + q * 4 - 0;               // col within this chunk's 32
            // lc4/q map covers cols 0..31 of the chunk (chunk base handled at load)
            uint2 hi, lo;
            split4(xv[q], hi, lo);
            *reinterpret_cast<uint2*>(&XH[b][lrow][(col & 31)]) = hi;
            *reinterpret_cast<uint2*>(&XL[b][lrow][(col & 31)]) = lo;
            split4(wv[q], hi, lo);
            *reinterpret_cast<uint2*>(&WH[b][lrow][(col & 31)]) = hi;
            *reinterpret_cast<uint2*>(&WL[b][lrow][(col & 31)]) = lo;
        }
        __syncthreads();

        // ---- issue LDGs for chunk c+1 (overlap with MMA below) ----
        if (c + 1 < NCH) {
            const int k0 = (c + 1) * KC;
#pragma unroll
            for (int q = 0; q < 4; q++) {
                // cols (k0 + (lc4+q*4)&31): lc4 16-offset alternates halves
                int cc = k0 + ((lc4 + q * 4) & 31);
                xv[q] = xok ? *reinterpret_cast<const float4*>(&x[(long)xrow * IN_DIM + cc])
                            : make_float4(0.f, 0.f, 0.f, 0.f);
                wv[q] = *reinterpret_cast<const float4*>(&W[(long)lrow * IN_DIM + cc]);
            }
        }

        // ---- MMA from buffer b ----
#pragma unroll
        for (int ks = 0; ks < 2; ks++) {
            const int kb = ks * 16 + qc;
            uint32_t a[2][4];
#pragma unroll
            for (int i = 0; i < 2; i++) {
                int r = warp_m * 32 + i * 16 + qr;
                a[i][0] = ld2(&XH[b][r][kb]);     a[i][1] = ld2(&XH[b][r + 8][kb]);
                a[i][2] = ld2(&XH[b][r][kb + 8]); a[i][3] = ld2(&XH[b][r + 8][kb + 8]);
            }
#pragma unroll
            for (int j = 0; j < 8; j++) {
                int n = warp_n * 64 + j * 8 + qr;
                uint32_t b0 = ld2(&WH[b][n][kb]), b1 = ld2(&WH[b][n][kb + 8]);
                mma16816(d[0][j], a[0], b0, b1);
                mma16816(d[1][j], a[1], b0, b1);
                uint32_t c0 = ld2(&WL[b][n][kb]), c1 = ld2(&WL[b][n][kb + 8]);
                mma16816(d[0][j], a[0], c0, c1);
                mma16816(d[1][j], a[1], c0, c1);
            }
#pragma unroll
            for (int i = 0; i < 2; i++) {
                int r = warp_m * 32 + i * 16 + qr;
                a[i][0] = ld2(&XL[b][r][kb]);     a[i][1] = ld2(&XL[b][r + 8][kb]);
                a[i][2] = ld2(&XL[b][r][kb + 8]); a[i][3] = ld2(&XL[b][r + 8][kb + 8]);
            }
#pragma unroll
            for (int j = 0; j < 8; j++) {
                int n = warp_n * 64 + j * 8 + qr;
                uint32_t b0 = ld2(&WH[b][n][kb]), b1 = ld2(&WH[b][n][kb + 8]);
                mma16816(d[0][j], a[0], b0, b1);
                mma16816(d[1][j], a[1], b0, b1);
            }
        }
        // single barrier per iteration: next STS targets the other buffer;
        // mma.sync register-completion orders the 2-apart buffer reuse.
    }

    // ---- epilogue: fp32 h + packed fp16 copy ----
    float*    hf  = reinterpret_cast<float*>(g_h);
    unsigned* hhu = reinterpret_cast<unsigned*>(g_hh);
#pragma unroll
    for (int i = 0; i < 2; i++) {
        int node0 = mBase + warp_m * 32 + i * 16 + qr;
        int node1 = node0 + 8;
#pragma unroll
        for (int j = 0; j < 8; j++) {
            int col = warp_n * 64 + j * 8 + qc;
            if (node0 < N_NODES) {
                *reinterpret_cast<float2*>(&hf[(long)node0 * HD + col]) =
                    make_float2(d[i][j][0], d[i][j][1]);
                hhu[node0 * 64 + (col >> 1)] = pack_h2(d[i][j][0], d[i][j][1]);
            }
            if (node1 < N_NODES) {
                *reinterpret_cast<float2*>(&hf[(long)node1 * HD + col]) =
                    make_float2(d[i][j][2], d[i][j][3]);
                hhu[node1 * 64 + (col >> 1)] = pack_h2(d[i][j][2], d[i][j][3]);
            }
        }
    }
}

// ---------------- 4. per-node attention scores (warp per node) ---------------
__global__ __launch_bounds__(256) void scores_kernel(const float* __restrict__ a_src,
                                                     const float* __restrict__ a_dst) {
    int warp = (blockIdx.x * blockDim.x + threadIdx.x) >> 5;
    if (warp >= N_NODES) return;
    int lane = threadIdx.x & 31;
    int head = lane >> 3;
    int sub  = lane & 7;

    float4 hv = g_h[warp * 32 + lane];
    const float4* as4 = reinterpret_cast<const float4*>(a_src);
    const float4* ad4 = reinterpret_cast<const float4*>(a_dst);
    float4 av = as4[head * 8 + sub];
    float4 dv = ad4[head * 8 + sub];

    float ps = hv.x * av.x + hv.y * av.y + hv.z * av.z + hv.w * av.w;
    float pd = hv.x * dv.x + hv.y * dv.y + hv.z * dv.z + hv.w * dv.w;
#pragma unroll
    for (int o = 4; o >= 1; o >>= 1) {
        ps += __shfl_xor_sync(0xffffffffu, ps, o);
        pd += __shfl_xor_sync(0xffffffffu, pd, o);
    }
    if (sub == 0) {
        reinterpret_cast<float*>(&g_ssrc[warp])[head] = ps;
        reinterpret_cast<float*>(&g_sdst[warp])[head] = pd;
    }
}

// ---------------- 5. edge scatter: ex + CSR placement ------------------------
// Softmax is shift-invariant and e = tanh(.)*w in (-1,1) is bounded, so the
// reference's segment_max subtraction is mathematically a no-op.
__global__ __launch_bounds__(256) void scatter_kernel(const int* __restrict__ idx,
                                                      const float* __restrict__ wts) {
    int e = blockIdx.x * blockDim.x + threadIdx.x;
    if (e >= N_EDGES) return;
    int2 p = reinterpret_cast<const int2*>(idx)[e];
    int s = p.x, d = p.y;
    float w = wts[e];
    float4 a = g_ssrc[s];
    float4 b = g_sdst[d];
    float4 ex;
    ex.x = expf(tanhf(a.x + b.x) * w);
    ex.y = expf(tanhf(a.y + b.y) * w);
    ex.z = expf(tanhf(a.z + b.z) * w);
    ex.w = expf(tanhf(a.w + b.w) * w);
    int pos = atomicAdd(&g_cursor[d], 1);
    g_csr_ex[pos]  = ex;
    g_csr_src[pos] = s;
}

// ---------------- 6. atomic-free aggregation + fused GELU (warp per dst) -----
__global__ __launch_bounds__(256) void aggregate_kernel(float* __restrict__ out) {
    int d = (blockIdx.x * blockDim.x + threadIdx.x) >> 5;
    if (d >= N_NODES) return;
    int lane = threadIdx.x & 31;

    int start = g_start[d];
    int end   = g_start[d + 1];

    const float* exf = reinterpret_cast<const float*>(g_csr_ex);

    int head = lane & 3;
    int esub = lane >> 2;
    float dsum = 0.f;
    for (int e = start + esub; e < end; e += 8)
        dsum += exf[e * 4 + head];
    dsum += __shfl_xor_sync(0xffffffffu, dsum, 4);
    dsum += __shfl_xor_sync(0xffffffffu, dsum, 8);
    dsum += __shfl_xor_sync(0xffffffffu, dsum, 16);
    int h2 = lane >> 3;
    float inv = 1.f / __shfl_sync(0xffffffffu, dsum, h2);

    const uint2* hh2 = reinterpret_cast<const uint2*>(g_hh);
    float4 acc = make_float4(0.f, 0.f, 0.f, 0.f);
#pragma unroll 4
    for (int e = start; e < end; e++) {
        int src = __ldg(&g_csr_src[e]);
        float alpha = exf[e * 4 + h2] * inv;
        uint2 raw = __ldg(&hh2[src * 32 + lane]);
        float2 f01 = unpack_h2(raw.x);
        float2 f23 = unpack_h2(raw.y);
        acc.x += alpha * f01.x; acc.y += alpha * f01.y;
        acc.z += alpha * f23.x; acc.w += alpha * f23.y;
    }

    const float r = 0.70710678118654752f;
    float4 v;
    v.x = 0.5f * acc.x * (1.f + erff(acc.x * r));
    v.y = 0.5f * acc.y * (1.f + erff(acc.y * r));
    v.z = 0.5f * acc.z * (1.f + erff(acc.z * r));
    v.w = 0.5f * acc.w * (1.f + erff(acc.w * r));
    reinterpret_cast<float4*>(out)[d * 32 + lane] = v;
}

// ---------------- launch -----------------------------------------------------
extern "C" void kernel_launch(void* const* d_in, const int* in_sizes, int n_in,
                              void* d_out, int out_size) {
    const float* x     = (const float*)d_in[0];
    const int*   idx   = (const int*)d_in[1];     // int64 stored as int32 pairs
    const float* wts   = (const float*)d_in[2];
    const float* W     = (const float*)d_in[3];
    const float* a_src = (const float*)d_in[4];
    const float* a_dst = (const float*)d_in[5];
    float* out = (float*)d_out;

    zero_count_kernel<<<SCAN_NBLK, SCAN_BLK>>>();                          // 1
    count_kernel<<<(N_EDGES + 255) / 256, 256>>>(idx);                     // 2
    scan_blocks_kernel<<<SCAN_NBLK, SCAN_BLK>>>();                         // 3
    gemm_hmma_kernel<<<(N_NODES + TILE_M - 1) / TILE_M, 256>>>(x, W);      // 4 <- profiled
    scan_tops_kernel<<<1, 64>>>();                                         // 5
    scores_kernel<<<(N_NODES * 32 + 255) / 256, 256>>>(a_src, a_dst);      // 6
    scan_apply_kernel<<<SCAN_NBLK, SCAN_BLK>>>();                          // 7
    scatter_kernel<<<(N_EDGES + 255) / 256, 256>>>(idx, wts);              // 8
    aggregate_kernel<<<(N_NODES * 32 + 255) / 256, 256>>>(out);            // 9
}

// round 11
// speedup vs baseline: 2.2699x; 1.0920x over previous
#include <cuda_runtime.h>
#include <cuda_fp16.h>
#include <cuda_bf16.h>
#include <cstdint>

constexpr int N_NODES = 50000;
constexpr int N_EDGES = 1600000;
constexpr int IN_DIM  = 256;
constexpr int HD      = 128;   // HEADS * OUT_DIM

constexpr int SCAN_BLK  = 1024;
constexpr int SCAN_NBLK = (N_NODES + SCAN_BLK - 1) / SCAN_BLK;   // 49

constexpr int TILE_M = 64;                 // smaller tile -> 2 CTAs/SM
constexpr int KC     = 32;                 // bf16 K-chunk
constexpr int KPAD   = 40;                 // smem row stride (conflict-free)
constexpr int NCH    = IN_DIM / KC;        // 8 chunks

// ---------------- scratch (static device globals) ----------------------------
__device__ uint4  g_hh[N_NODES * (HD / 8)];  // h fp16 packed (12.8 MB) — only h copy
__device__ float4 g_ssrc[N_NODES];           // per-node src scores (atomic-built)
__device__ float4 g_sdst[N_NODES];
__device__ float4 g_csr_ex[N_EDGES];
__device__ int    g_csr_src[N_EDGES];
__device__ int    g_count[N_NODES];
__device__ int    g_start[N_NODES + 1];
__device__ int    g_cursor[N_NODES];
__device__ int    g_blocksum[SCAN_NBLK];

// ---------------- helpers ----------------------------------------------------
__device__ __forceinline__ unsigned pack_h2(float a, float b) {   // fp16 pair
    __half2 h = __float22half2_rn(make_float2(a, b));
    return *reinterpret_cast<unsigned*>(&h);
}
__device__ __forceinline__ float2 unpack_h2(unsigned u) {
    __half2 h = *reinterpret_cast<__half2*>(&u);
    return __half22float2(h);
}
__device__ __forceinline__ unsigned pack_bf2(__nv_bfloat16 a, __nv_bfloat16 b) {
    __nv_bfloat162 t = __halves2bfloat162(a, b);
    return *reinterpret_cast<unsigned*>(&t);
}
__device__ __forceinline__ uint32_t ld2(const uint16_t* p) {
    return *reinterpret_cast<const uint32_t*>(p);
}
// HMMA bf16: m16n8k16, row.col, fp32 accumulate (baseline PTX, sm_80+)
__device__ __forceinline__ void mma16816(float* d, const uint32_t* a,
                                         uint32_t b0, uint32_t b1) {
    asm volatile(
        "mma.sync.aligned.m16n8k16.row.col.f32.bf16.bf16.f32 "
        "{%0,%1,%2,%3}, {%4,%5,%6,%7}, {%8,%9}, {%0,%1,%2,%3};"
        : "+f"(d[0]), "+f"(d[1]), "+f"(d[2]), "+f"(d[3])
        : "r"(a[0]), "r"(a[1]), "r"(a[2]), "r"(a[3]), "r"(b0), "r"(b1));
}
// split fp32 -> (hi, lo) bf16 pair packs for 4 consecutive values
__device__ __forceinline__ void split4(float4 v, uint2& hi, uint2& lo) {
    __nv_bfloat16 h0 = __float2bfloat16_rn(v.x);
    __nv_bfloat16 h1 = __float2bfloat16_rn(v.y);
    __nv_bfloat16 h2 = __float2bfloat16_rn(v.z);
    __nv_bfloat16 h3 = __float2bfloat16_rn(v.w);
    hi = make_uint2(pack_bf2(h0, h1), pack_bf2(h2, h3));
    lo = make_uint2(pack_bf2(__float2bfloat16_rn(v.x - __bfloat162float(h0)),
                             __float2bfloat16_rn(v.y - __bfloat162float(h1))),
                    pack_bf2(__float2bfloat16_rn(v.z - __bfloat162float(h2)),
                             __float2bfloat16_rn(v.w - __bfloat162float(h3))));
}

// ---------------- 0. zero counters + score accumulators ----------------------
__global__ __launch_bounds__(SCAN_BLK) void zero_kernel() {
    int n = blockIdx.x * SCAN_BLK + threadIdx.x;
    if (n < N_NODES) {
        g_count[n] = 0;
        g_ssrc[n] = make_float4(0.f, 0.f, 0.f, 0.f);
        g_sdst[n] = make_float4(0.f, 0.f, 0.f, 0.f);
    }
}

// ---------------- 1. in-degree histogram -------------------------------------
__global__ __launch_bounds__(256) void count_kernel(const int* __restrict__ idx) {
    int e = blockIdx.x * blockDim.x + threadIdx.x;
    if (e >= N_EDGES) return;
    int2 p = reinterpret_cast<const int2*>(idx)[e];
    atomicAdd(&g_count[p.y], 1);
}

// ---------------- 2. hierarchical prefix sum ---------------------------------
__global__ __launch_bounds__(SCAN_BLK) void scan_blocks_kernel() {
    __shared__ int sh[SCAN_BLK];
    int tid = threadIdx.x;
    int n = blockIdx.x * SCAN_BLK + tid;
    int v = (n < N_NODES) ? g_count[n] : 0;
    sh[tid] = v;
    __syncthreads();
#pragma unroll
    for (int off = 1; off < SCAN_BLK; off <<= 1) {
        int t = (tid >= off) ? sh[tid - off] : 0;
        __syncthreads();
        sh[tid] += t;
        __syncthreads();
    }
    if (n < N_NODES) g_start[n] = sh[tid] - v;
    if (tid == SCAN_BLK - 1) g_blocksum[blockIdx.x] = sh[tid];
}
__global__ __launch_bounds__(64) void scan_tops_kernel() {
    __shared__ int sh[64];
    int tid = threadIdx.x;
    int v = (tid < SCAN_NBLK) ? g_blocksum[tid] : 0;
    sh[tid] = v;
    __syncthreads();
#pragma unroll
    for (int off = 1; off < 64; off <<= 1) {
        int t = (tid >= off) ? sh[tid - off] : 0;
        __syncthreads();
        sh[tid] += t;
        __syncthreads();
    }
    if (tid < SCAN_NBLK) g_blocksum[tid] = sh[tid] - v;
}
__global__ __launch_bounds__(SCAN_BLK) void scan_apply_kernel() {
    int n = blockIdx.x * SCAN_BLK + threadIdx.x;
    if (n >= N_NODES) return;
    int s = g_start[n] + g_blocksum[blockIdx.x];
    g_start[n]  = s;
    g_cursor[n] = s;
    if (n == 0) g_start[N_NODES] = N_EDGES;
}

// ---------------- 3. pipelined HMMA GEMM + fused scores ----------------------
// h = x_hi*W_hi + x_hi*W_lo + x_lo*W_hi (fp32 acc). Epilogue: packed fp16 h
// AND per-node attention scores s_src/s_dst via fp32 atomics (h never stored
// in fp32 at all).
// 8 warps as 4(m) x 2(n); warp tile 16x64 = 1x8 m16n8k16 fragments.
__global__ __launch_bounds__(256, 2) void gemm_fused_kernel(
        const float* __restrict__ x, const float* __restrict__ W,
        const float* __restrict__ a_src, const float* __restrict__ a_dst) {
    __shared__ uint16_t XH[2][TILE_M][KPAD];
    __shared__ uint16_t XL[2][TILE_M][KPAD];
    __shared__ uint16_t WH[2][HD][KPAD];
    __shared__ uint16_t WL[2][HD][KPAD];

    const int tid  = threadIdx.x;
    const int wid  = tid >> 5;
    const int lane = tid & 31;
    const int warp_m = wid >> 1;        // 0..3 -> rows 16*warp_m
    const int warp_n = wid & 1;         // 0..1 -> cols 64*warp_n
    const int mBase = blockIdx.x * TILE_M;

    const int qr = lane >> 2;           // 0..7
    const int qc = (lane & 3) * 2;      // 0,2,4,6

    // load maps: X = 64 rows x 8 float4 (512 slots, 2/thread),
    //            W = 128 rows x 8 float4 (1024 slots, 4/thread)
    const int xr0 = tid >> 3,        xc0 = (tid & 7) * 4;          // slot tid
    const int xr1 = (256 + tid) >> 3, xc1 = ((256 + tid) & 7) * 4; // slot 256+tid

    float d[8][4];
#pragma unroll
    for (int j = 0; j < 8; j++)
#pragma unroll
        for (int t = 0; t < 4; t++) d[j][t] = 0.f;

    float4 xv[2], wv[4];
    const bool xok0 = (mBase + xr0 < N_NODES);
    const bool xok1 = (mBase + xr1 < N_NODES);
    // prologue: chunk 0
    xv[0] = xok0 ? *reinterpret_cast<const float4*>(&x[(long)(mBase + xr0) * IN_DIM + xc0])
                 : make_float4(0.f, 0.f, 0.f, 0.f);
    xv[1] = xok1 ? *reinterpret_cast<const float4*>(&x[(long)(mBase + xr1) * IN_DIM + xc1])
                 : make_float4(0.f, 0.f, 0.f, 0.f);
#pragma unroll
    for (int q = 0; q < 4; q++) {
        int i = q * 256 + tid;
        wv[q] = *reinterpret_cast<const float4*>(&W[(long)(i >> 3) * IN_DIM + (i & 7) * 4]);
    }

    for (int c = 0; c < NCH; c++) {
        const int b = c & 1;
        // ---- convert prefetched regs -> smem buffer b ----
        {
            uint2 hi, lo;
            split4(xv[0], hi, lo);
            *reinterpret_cast<uint2*>(&XH[b][xr0][xc0]) = hi;
            *reinterpret_cast<uint2*>(&XL[b][xr0][xc0]) = lo;
            split4(xv[1], hi, lo);
            *reinterpret_cast<uint2*>(&XH[b][xr1][xc1]) = hi;
            *reinterpret_cast<uint2*>(&XL[b][xr1][xc1]) = lo;
#pragma unroll
            for (int q = 0; q < 4; q++) {
                int i = q * 256 + tid;
                split4(wv[q], hi, lo);
                *reinterpret_cast<uint2*>(&WH[b][i >> 3][(i & 7) * 4]) = hi;
                *reinterpret_cast<uint2*>(&WL[b][i >> 3][(i & 7) * 4]) = lo;
            }
        }
        __syncthreads();

        // ---- issue LDGs for chunk c+1 (overlap with MMA below) ----
        if (c + 1 < NCH) {
            const int k0 = (c + 1) * KC;
            xv[0] = xok0 ? *reinterpret_cast<const float4*>(&x[(long)(mBase + xr0) * IN_DIM + k0 + xc0])
                         : make_float4(0.f, 0.f, 0.f, 0.f);
            xv[1] = xok1 ? *reinterpret_cast<const float4*>(&x[(long)(mBase + xr1) * IN_DIM + k0 + xc1])
                         : make_float4(0.f, 0.f, 0.f, 0.f);
#pragma unroll
            for (int q = 0; q < 4; q++) {
                int i = q * 256 + tid;
                wv[q] = *reinterpret_cast<const float4*>(&W[(long)(i >> 3) * IN_DIM + k0 + (i & 7) * 4]);
            }
        }

        // ---- MMA from buffer b ----
#pragma unroll
        for (int ks = 0; ks < 2; ks++) {
            const int kb = ks * 16 + qc;
            const int r = warp_m * 16 + qr;
            uint32_t a[4];
            a[0] = ld2(&XH[b][r][kb]);     a[1] = ld2(&XH[b][r + 8][kb]);
            a[2] = ld2(&XH[b][r][kb + 8]); a[3] = ld2(&XH[b][r + 8][kb + 8]);
#pragma unroll
            for (int j = 0; j < 8; j++) {
                int n = warp_n * 64 + j * 8 + qr;
                uint32_t b0 = ld2(&WH[b][n][kb]), b1 = ld2(&WH[b][n][kb + 8]);
                mma16816(d[j], a, b0, b1);
                uint32_t c0 = ld2(&WL[b][n][kb]), c1 = ld2(&WL[b][n][kb + 8]);
                mma16816(d[j], a, c0, c1);
            }
            a[0] = ld2(&XL[b][r][kb]);     a[1] = ld2(&XL[b][r + 8][kb]);
            a[2] = ld2(&XL[b][r][kb + 8]); a[3] = ld2(&XL[b][r + 8][kb + 8]);
#pragma unroll
            for (int j = 0; j < 8; j++) {
                int n = warp_n * 64 + j * 8 + qr;
                uint32_t b0 = ld2(&WH[b][n][kb]), b1 = ld2(&WH[b][n][kb + 8]);
                mma16816(d[j], a, b0, b1);
            }
        }
        // single barrier/iter: next STS hits the other buffer.
    }

    // ---- epilogue: packed fp16 h + fused attention scores ----
    unsigned* hhu = reinterpret_cast<unsigned*>(g_hh);
    float* ssrcf = reinterpret_cast<float*>(g_ssrc);
    float* sdstf = reinterpret_cast<float*>(g_sdst);

    const int node0 = mBase + warp_m * 16 + qr;
    const int node1 = node0 + 8;

    // per-thread score partials: this warp's 64 cols span 2 heads
    float ps0[2] = {0.f, 0.f}, pd0[2] = {0.f, 0.f};
    float ps1[2] = {0.f, 0.f}, pd1[2] = {0.f, 0.f};
#pragma unroll
    for (int j = 0; j < 8; j++) {
        int colb = warp_n * 64 + j * 8 + qc;          // even; pair stays in head
        int hl   = (j * 8 + qc) >> 5;                 // 0/1 within warp's heads
        int head = warp_n * 2 + hl;
#pragma unroll
        for (int t = 0; t < 2; t++) {
            int dim = (colb + t) & 31;
            float asv = __ldg(&a_src[head * 32 + dim]);
            float adv = __ldg(&a_dst[head * 32 + dim]);
            ps0[hl] += d[j][t] * asv;     pd0[hl] += d[j][t] * adv;
            ps1[hl] += d[j][2 + t] * asv; pd1[hl] += d[j][2 + t] * adv;
        }
        if (node0 < N_NODES)
            hhu[node0 * 64 + (colb >> 1)] = pack_h2(d[j][0], d[j][1]);
        if (node1 < N_NODES)
            hhu[node1 * 64 + (colb >> 1)] = pack_h2(d[j][2], d[j][3]);
    }
#pragma unroll
    for (int hl = 0; hl < 2; hl++) {
        int head = warp_n * 2 + hl;
        if (node0 < N_NODES) {
            atomicAdd(&ssrcf[node0 * 4 + head], ps0[hl]);
            atomicAdd(&sdstf[node0 * 4 + head], pd0[hl]);
        }
        if (node1 < N_NODES) {
            atomicAdd(&ssrcf[node1 * 4 + head], ps1[hl]);
            atomicAdd(&sdstf[node1 * 4 + head], pd1[hl]);
        }
    }
}

// ---------------- 5. edge scatter: ex + CSR placement ------------------------
// Softmax is shift-invariant and e = tanh(.)*w in (-1,1) is bounded, so the
// reference's segment_max subtraction is mathematically a no-op.
__global__ __launch_bounds__(256) void scatter_kernel(const int* __restrict__ idx,
                                                      const float* __restrict__ wts) {
    int e = blockIdx.x * blockDim.x + threadIdx.x;
    if (e >= N_EDGES) return;
    int2 p = reinterpret_cast<const int2*>(idx)[e];
    int s = p.x, d = p.y;
    float w = wts[e];
    float4 a = g_ssrc[s];
    float4 b = g_sdst[d];
    float4 ex;
    ex.x = expf(tanhf(a.x + b.x) * w);
    ex.y = expf(tanhf(a.y + b.y) * w);
    ex.z = expf(tanhf(a.z + b.z) * w);
    ex.w = expf(tanhf(a.w + b.w) * w);
    int pos = atomicAdd(&g_cursor[d], 1);
    g_csr_ex[pos]  = ex;
    g_csr_src[pos] = s;
}

// ---------------- 6. single-pass aggregation + fused GELU (warp per dst) -----
// out = (sum_e ex_e * h_src) / (sum_e ex_e)  — denom fused into gather loop.
__global__ __launch_bounds__(256) void aggregate_kernel(float* __restrict__ out) {
    int d = (blockIdx.x * blockDim.x + threadIdx.x) >> 5;
    if (d >= N_NODES) return;
    int lane = threadIdx.x & 31;
    int h2 = lane >> 3;                 // head owning my out cols

    int start = g_start[d];
    int end   = g_start[d + 1];

    const float* exf = reinterpret_cast<const float*>(g_csr_ex);
    const uint2* hh2 = reinterpret_cast<const uint2*>(g_hh);

    float dsum = 0.f;
    float4 acc = make_float4(0.f, 0.f, 0.f, 0.f);
#pragma unroll 4
    for (int e = start; e < end; e++) {
        int src = __ldg(&g_csr_src[e]);          // warp-uniform broadcast
        float exv = __ldg(&exf[e * 4 + h2]);
        uint2 raw = __ldg(&hh2[src * 32 + lane]);
        dsum += exv;
        float2 f01 = unpack_h2(raw.x);
        float2 f23 = unpack_h2(raw.y);
        acc.x += exv * f01.x; acc.y += exv * f01.y;
        acc.z += exv * f23.x; acc.w += exv * f23.y;
    }
    float inv = (end > start) ? 1.f / dsum : 0.f;   // deg==0 -> out 0 (= ref)

    const float r = 0.70710678118654752f;
    float4 v;
    acc.x *= inv; acc.y *= inv; acc.z *= inv; acc.w *= inv;
    v.x = 0.5f * acc.x * (1.f + erff(acc.x * r));
    v.y = 0.5f * acc.y * (1.f + erff(acc.y * r));
    v.z = 0.5f * acc.z * (1.f + erff(acc.z * r));
    v.w = 0.5f * acc.w * (1.f + erff(acc.w * r));
    reinterpret_cast<float4*>(out)[d * 32 + lane] = v;
}

// ---------------- launch -----------------------------------------------------
extern "C" void kernel_launch(void* const* d_in, const int* in_sizes, int n_in,
                              void* d_out, int out_size) {
    const float* x     = (const float*)d_in[0];
    const int*   idx   = (const int*)d_in[1];     // int64 stored as int32 pairs
    const float* wts   = (const float*)d_in[2];
    const float* W     = (const float*)d_in[3];
    const float* a_src = (const float*)d_in[4];
    const float* a_dst = (const float*)d_in[5];
    float* out = (float*)d_out;

    zero_kernel<<<SCAN_NBLK, SCAN_BLK>>>();                               // 1
    count_kernel<<<(N_EDGES + 255) / 256, 256>>>(idx);                    // 2
    scan_blocks_kernel<<<SCAN_NBLK, SCAN_BLK>>>();                        // 3
    gemm_fused_kernel<<<(N_NODES + TILE_M - 1) / TILE_M, 256>>>(
        x, W, a_src, a_dst);                                              // 4 <- profiled
    scan_tops_kernel<<<1, 64>>>();                                        // 5
    scan_apply_kernel<<<SCAN_NBLK, SCAN_BLK>>>();                         // 6
    scatter_kernel<<<(N_EDGES + 255) / 256, 256>>>(idx, wts);             // 7
    aggregate_kernel<<<(N_NODES * 32 + 255) / 256, 256>>>(out);           // 8
}